// round 12
// baseline (speedup 1.0000x reference)
#include <cuda_runtime.h>
#include <cuda_bf16.h>
#include <mma.h>
#include <cstdint>

using namespace nvcuda;

#define Bn 32768
#define Fn 512
#define En 8
#define Hn 128
#define An 256
#define Tn 8
#define HCn 32
#define MT 128
#define NTILES_MAX 264

// ---- smem layout (bytes) ----
#define XS0   0         // 2 x 12288 x tiles ([128][24] bf16 hi at +0 (6144), lo at +6144)
#define BT0   24576     // weight tile buffers: 2 x 8704 ([16][136] bf16 hi at +0, lo at +4352)
#define HH    41984     // [128][136] bf16 (34816) -- h hi only (2-term GEMM2)
#define RIDX  76800
#define ACTS  77312
#define AB1   77824
#define AB2   78336
#define CB1   79360
#define CW2S  79488
#define SMEM_TOTAL 79616

// ---- device scratch ----
__device__ int g_acnt[En];
__device__ int g_ccnt[Tn];
__device__ int g_alist[En * Bn];
__device__ int g_clist[Tn * Bn];
__device__ __nv_bfloat16 g_aw1h[En * Fn * Hn];
__device__ __nv_bfloat16 g_aw1l[En * Fn * Hn];
__device__ __nv_bfloat16 g_aw2h[En * Hn * An];
__device__ __nv_bfloat16 g_aw2l[En * Hn * An];
__device__ __nv_bfloat16 g_cw1h[Tn * Fn * HCn];
__device__ __nv_bfloat16 g_cw1l[Tn * Fn * HCn];

typedef wmma::fragment<wmma::matrix_a, 16, 16, 16, __nv_bfloat16, wmma::row_major> FragA;
typedef wmma::fragment<wmma::matrix_b, 16, 16, 16, __nv_bfloat16, wmma::row_major> FragB;
typedef wmma::fragment<wmma::accumulator, 16, 16, 16, float> FragC;

// ---------------- routing ----------------
__global__ void zero_kernel() {
    int t = threadIdx.x;
    if (t < En) g_acnt[t] = 0;
    if (t < Tn) g_ccnt[t] = 0;
}

__global__ void route_kernel(const int* __restrict__ commands,
                             const int* __restrict__ tasks) {
    __shared__ int scA[En], scC[Tn], baseA[En], baseC[Tn];
    int tid = threadIdx.x;
    if (tid < En) scA[tid] = 0;
    if (tid < Tn) scC[tid] = 0;
    __syncthreads();
    int b = blockIdx.x * blockDim.x + tid;
    int e = commands[b];
    int pa = atomicAdd(&scA[e], 1);
    int t = tasks[b];
    int pc = atomicAdd(&scC[t], 1);
    __syncthreads();
    if (tid < En) baseA[tid] = atomicAdd(&g_acnt[tid], scA[tid]);
    if (tid < Tn) baseC[tid] = atomicAdd(&g_ccnt[tid], scC[tid]);
    __syncthreads();
    g_alist[e * Bn + baseA[e] + pa] = b;
    g_clist[t * Bn + baseC[t] + pc] = b;
}

// ---------------- weight split prep ----------------
__global__ void prep_kernel(const float* __restrict__ AW1, const float* __restrict__ AW2,
                            const float* __restrict__ CW1) {
    int i = blockIdx.x * 256 + threadIdx.x;
    if (i < En * Fn * Hn) {
        float f = AW1[i];
        __nv_bfloat16 h = __float2bfloat16(f);
        g_aw1h[i] = h;
        g_aw1l[i] = __float2bfloat16(f - __bfloat162float(h));
    } else if (i < En * Fn * Hn + En * Hn * An) {
        int j = i - En * Fn * Hn;
        float f = AW2[j];
        __nv_bfloat16 h = __float2bfloat16(f);
        g_aw2h[j] = h;
        g_aw2l[j] = __float2bfloat16(f - __bfloat162float(h));
    } else if (i < En * Fn * Hn + En * Hn * An + Tn * Fn * HCn) {
        int j = i - En * Fn * Hn - En * Hn * An;
        float f = CW1[j];
        __nv_bfloat16 h = __float2bfloat16(f);
        g_cw1h[j] = h;
        g_cw1l[j] = __float2bfloat16(f - __bfloat162float(h));
    }
}

// ---------------- helpers ----------------
__device__ __forceinline__ uint32_t pk(float a, float b) {
    __nv_bfloat162 t = __floats2bfloat162_rn(a, b);
    return *reinterpret_cast<uint32_t*>(&t);
}

__device__ __forceinline__ void split8(const float* f, uint4& hi, uint4& lo) {
    float fh[8], fl[8];
#pragma unroll
    for (int i = 0; i < 8; i++) {
        float h = __bfloat162float(__float2bfloat16(f[i]));
        fh[i] = h;
        fl[i] = f[i] - h;
    }
    hi = make_uint4(pk(fh[0], fh[1]), pk(fh[2], fh[3]), pk(fh[4], fh[5]), pk(fh[6], fh[7]));
    lo = make_uint4(pk(fl[0], fl[1]), pk(fl[2], fl[3]), pk(fl[4], fl[5]), pk(fl[6], fl[7]));
}

__device__ __forceinline__ uint32_t s2u(const void* p) {
    return (uint32_t)__cvta_generic_to_shared(p);
}
__device__ __forceinline__ void cpa(uint32_t d, const void* s) {
    asm volatile("cp.async.cg.shared.global [%0], [%1], 16;" :: "r"(d), "l"(s));
}
#define CPC() asm volatile("cp.async.commit_group;")
#define CPW1() asm volatile("cp.async.wait_group 1;")
#define CPW0() asm volatile("cp.async.wait_group 0;")

// load 8 fp32 of this thread's row slice (16-col slice, lane pair splits 8/8)
__device__ __forceinline__ void ldx8(float* r, const float* __restrict__ x, int grow,
                                     int kc, int tid) {
    const float4* s = (const float4*)(x + (size_t)grow * Fn + kc * 16 + (tid & 1) * 8);
    float4 v;
    v = s[0]; r[0] = v.x; r[1] = v.y; r[2] = v.z; r[3] = v.w;
    v = s[1]; r[4] = v.x; r[5] = v.y; r[6] = v.z; r[7] = v.w;
}

// split regs, store into XS buffer b ([128][24] bf16, hi at +0, lo at +6144)
__device__ __forceinline__ void stx8(unsigned char* sm, int b, const float* r, int tid) {
    uint4 hi, lo;
    split8(r, hi, lo);
    uint32_t a = (uint32_t)((tid >> 1) * 48 + (tid & 1) * 16);
    *(uint4*)(sm + XS0 + b * 12288 + a) = hi;
    *(uint4*)(sm + XS0 + b * 12288 + 6144 + a) = lo;
}

// W1 slice kc16 (16 k-rows x 128 cols) -> BT buffer (hi +0, lo +4352, stride 272B)
// 256 threads: k = tid>>4, seg = tid&15 (16B segments)
__device__ __forceinline__ void issue_w1(unsigned char* sm, int b, int grp, int kc16, int tid) {
    int k = tid >> 4, seg = tid & 15;
    size_t gb = (((size_t)grp * Fn + kc16 * 16 + k) << 7) + seg * 8;
    uint32_t d = s2u(sm + BT0) + b * 8704 + k * 272 + seg * 16;
    cpa(d, g_aw1h + gb);
    cpa(d + 4352, g_aw1l + gb);
}
// W2 slice kcg (0..15): N-half = kcg>>3, local k-slice = kcg&7
__device__ __forceinline__ void issue_w2(unsigned char* sm, int b, int grp, int kcg, int tid) {
    int k = tid >> 4, seg = tid & 15;
    size_t gb = ((size_t)grp * Hn + (kcg & 7) * 16 + k) * An + (kcg >> 3) * 128 + seg * 8;
    uint32_t d = s2u(sm + BT0) + b * 8704 + k * 272 + seg * 16;
    cpa(d, g_aw2h + gb);
    cpa(d + 4352, g_aw2l + gb);
}
// critic W1 slice (16 x 32), buffer b at BT0 + b*2560 (hi stride 80B, lo +1280)
__device__ __forceinline__ void issue_cw(unsigned char* sm, int b, int grp, int kc16, int tid) {
    if (tid < 64) {
        int row = tid >> 2, seg = tid & 3;
        size_t gb = ((size_t)grp * Fn + kc16 * 16 + row) * HCn + seg * 8;
        uint32_t d = s2u(sm + BT0) + b * 2560 + row * 80 + seg * 16;
        cpa(d, g_cw1h + gb);
        cpa(d + 1280, g_cw1l + gb);
    }
}

// ---------------- fused actor + critic ----------------
extern "C" __global__ void __launch_bounds__(256, 2)
fused_kernel(const float* __restrict__ x, const int* __restrict__ actions,
             const float* __restrict__ Ab1, const float* __restrict__ Ab2,
             const float* __restrict__ Cb1, const float* __restrict__ CW2,
             const float* __restrict__ Cb2, float* __restrict__ out) {
    extern __shared__ unsigned char sm[];
    int tid = threadIdx.x;
    int wid = tid >> 5;
    int wm = wid >> 1;   // 0..3: 32-row group
    int wn = wid & 1;    // 0..1: 64-col group
    bool is_actor = (blockIdx.z == 0);

    int grp = -1, local = blockIdx.x;
    const int* cnts = is_actor ? g_acnt : g_ccnt;
#pragma unroll
    for (int i = 0; i < En; i++) {
        int nt = (cnts[i] + MT - 1) / MT;
        if (grp < 0) {
            if (local < nt) grp = i;
            else local -= nt;
        }
    }
    if (grp < 0) return;
    int cnt = cnts[grp];
    int r0 = local * MT;

    int* ridx = (int*)(sm + RIDX);
    int* acts = (int*)(sm + ACTS);
    if (tid < MT) {
        int r = r0 + tid;
        const int* list = is_actor ? (g_alist + grp * Bn) : (g_clist + grp * Bn);
        int idx = (r < cnt) ? list[r] : -1;
        ridx[tid] = idx;
        if (is_actor) acts[tid] = (idx >= 0) ? actions[idx] : 0;
    }
    if (is_actor) {
        if (tid < Hn) ((float*)(sm + AB1))[tid] = Ab1[grp * Hn + tid];
        ((float*)(sm + AB2))[tid] = Ab2[grp * An + tid];
    } else if (tid < HCn) {
        ((float*)(sm + CB1))[tid] = Cb1[grp * HCn + tid];
        ((float*)(sm + CW2S))[tid] = CW2[grp * HCn + tid];
    }
    __syncthreads();
    int rr = ridx[tid >> 1];
    int grow = rr < 0 ? 0 : rr;
    float xr[8];
    float* stg = (float*)(sm + XS0);  // f32 staging [128][36] over dead XS region

    if (is_actor) {
        // ======== GEMM1: h = x @ W1 [128 x 512 x 128], K-slice 16, pipelined ====
        FragC acc[2][4];
#pragma unroll
        for (int mi = 0; mi < 2; mi++)
#pragma unroll
            for (int ni = 0; ni < 4; ni++) wmma::fill_fragment(acc[mi][ni], 0.f);

        ldx8(xr, x, grow, 0, tid);
        stx8(sm, 0, xr, tid);
        ldx8(xr, x, grow, 1, tid);
        issue_w1(sm, 0, grp, 0, tid);
        CPC();

        for (int kc = 0; kc < 32; kc++) {
            int b = kc & 1;
            // (A): all threads finished reading BT[b^1] (at kc-1) before refilling it
            __syncthreads();
            if (kc < 31) issue_w1(sm, b ^ 1, grp, kc + 1, tid);
            else issue_w2(sm, 0, grp, 0, tid);  // prefetch GEMM2 kcg0 -> buf0
            CPC();
            CPW1();
            // (B): cross-thread visibility of BT[b] + XS[b]
            __syncthreads();
            const __nv_bfloat16* xh = (const __nv_bfloat16*)(sm + XS0 + b * 12288);
            const __nv_bfloat16* bh = (const __nv_bfloat16*)(sm + BT0 + b * 8704);
            FragA ah[2], al[2];
#pragma unroll
            for (int mi = 0; mi < 2; mi++) {
                wmma::load_matrix_sync(ah[mi], xh + (wm * 32 + mi * 16) * 24, 24);
                wmma::load_matrix_sync(al[mi], xh + 3072 + (wm * 32 + mi * 16) * 24, 24);
            }
#pragma unroll
            for (int ni = 0; ni < 4; ni++) {
                FragB fbh, fbl;
                wmma::load_matrix_sync(fbh, bh + wn * 64 + ni * 16, 136);
                wmma::load_matrix_sync(fbl, bh + 2176 + wn * 64 + ni * 16, 136);
#pragma unroll
                for (int mi = 0; mi < 2; mi++) {
                    wmma::mma_sync(acc[mi][ni], ah[mi], fbh, acc[mi][ni]);
                    wmma::mma_sync(acc[mi][ni], ah[mi], fbl, acc[mi][ni]);
                    wmma::mma_sync(acc[mi][ni], al[mi], fbh, acc[mi][ni]);
                }
            }
            if (kc < 31) {
                stx8(sm, b ^ 1, xr, tid);
                if (kc < 30) ldx8(xr, x, grow, kc + 2, tid);
            }
        }

        // ---- GEMM1 epilogue: 4 passes of 32 cols via XS staging; h hi only ----
        __syncthreads();
#pragma unroll 1
        for (int p = 0; p < 4; p++) {
            if (wn == (p >> 1)) {
                int j0 = (p & 1) * 2;
#pragma unroll
                for (int mi = 0; mi < 2; mi++)
#pragma unroll
                    for (int j = 0; j < 2; j++)
                        wmma::store_matrix_sync(stg + (wm * 32 + mi * 16) * 36 + j * 16,
                                                acc[mi][j0 + j], 36, wmma::mem_row_major);
            }
            __syncthreads();
            int row = tid >> 1, cl = (tid & 1) * 16;
            const float* sp = stg + row * 36 + cl;
            const float* bp = (const float*)(sm + AB1) + p * 32 + cl;
#pragma unroll
            for (int g = 0; g < 2; g++) {
                float f[8];
#pragma unroll
                for (int i = 0; i < 8; i++) {
                    float h = sp[g * 8 + i] + bp[g * 8 + i];
                    f[i] = h > 0.f ? h : 0.f;
                }
                uint4 hi = make_uint4(pk(f[0], f[1]), pk(f[2], f[3]),
                                      pk(f[4], f[5]), pk(f[6], f[7]));
                *(uint4*)(sm + HH + (row * 136 + p * 32 + cl + g * 8) * 2) = hi;
            }
            __syncthreads();
        }

        // ======== GEMM2: scores = h_hi @ (W2h + W2l), 2-term, online softmax ===
        float mrun = -3e38f, zrun = 0.f, s1run = 0.f, schrun = -3e38f;
        int myact = acts[tid >> 1];
        FragC a2[2][4];
#pragma unroll 1
        for (int half = 0; half < 2; half++) {
#pragma unroll
            for (int mi = 0; mi < 2; mi++)
#pragma unroll
                for (int ni = 0; ni < 4; ni++) wmma::fill_fragment(a2[mi][ni], 0.f);
#pragma unroll 1
            for (int kcl = 0; kcl < 8; kcl++) {
                int kcg = half * 8 + kcl;
                int b = kcg & 1;
                // (A): previous consumers of BT[b^1] done before refill
                __syncthreads();
                if (kcg < 15) {
                    issue_w2(sm, b ^ 1, grp, kcg + 1, tid);
                    CPC();
                    CPW1();
                } else {
                    CPW0();
                }
                // (B): cross-thread visibility of BT[b]
                __syncthreads();
                const __nv_bfloat16* bh = (const __nv_bfloat16*)(sm + BT0 + b * 8704);
                FragA ah[2];
#pragma unroll
                for (int mi = 0; mi < 2; mi++)
                    wmma::load_matrix_sync(ah[mi], (const __nv_bfloat16*)(sm + HH) +
                        (wm * 32 + mi * 16) * 136 + kcl * 16, 136);
#pragma unroll
                for (int ni = 0; ni < 4; ni++) {
                    FragB fbh, fbl;
                    wmma::load_matrix_sync(fbh, bh + wn * 64 + ni * 16, 136);
                    wmma::load_matrix_sync(fbl, bh + 2176 + wn * 64 + ni * 16, 136);
#pragma unroll
                    for (int mi = 0; mi < 2; mi++) {
                        wmma::mma_sync(a2[mi][ni], ah[mi], fbh, a2[mi][ni]);
                        wmma::mma_sync(a2[mi][ni], ah[mi], fbl, a2[mi][ni]);
                    }
                }
            }
            // ---- half epilogue: 4 passes of 32 cols via XS staging ----
            __syncthreads();
#pragma unroll 1
            for (int p = 0; p < 4; p++) {
                if (wn == (p >> 1)) {
                    int j0 = (p & 1) * 2;
#pragma unroll
                    for (int mi = 0; mi < 2; mi++)
#pragma unroll
                        for (int j = 0; j < 2; j++)
                            wmma::store_matrix_sync(stg + (wm * 32 + mi * 16) * 36 + j * 16,
                                                    a2[mi][j0 + j], 36, wmma::mem_row_major);
                }
                __syncthreads();
                int row = tid >> 1, cl = (tid & 1) * 16;
                int abase = half * 128 + p * 32 + cl;
                const float* sp = stg + row * 36 + cl;
                const float* bp = (const float*)(sm + AB2) + abase;
                float s[16];
                float mx = -3e38f;
#pragma unroll
                for (int c = 0; c < 16; c++) {
                    s[c] = sp[c] + bp[c];
                    mx = fmaxf(mx, s[c]);
                }
                float z = 0.f, s1 = 0.f, sch = -3e38f;
#pragma unroll
                for (int c = 0; c < 16; c++) {
                    float pv = __expf(s[c] - mx);
                    z += pv;
                    s1 += s[c] * pv;
                    if (abase + c == myact) sch = s[c];
                }
                float mo = __shfl_xor_sync(0xffffffffu, mx, 1);
                float zo = __shfl_xor_sync(0xffffffffu, z, 1);
                float so = __shfl_xor_sync(0xffffffffu, s1, 1);
                float co = __shfl_xor_sync(0xffffffffu, sch, 1);
                float M = fmaxf(mx, mo);
                float f1 = __expf(mx - M), f2 = __expf(mo - M);
                z = z * f1 + zo * f2;
                s1 = s1 * f1 + so * f2;
                sch = fmaxf(sch, co);
                float MM = fmaxf(mrun, M);
                float g1 = __expf(mrun - MM), g2 = __expf(M - MM);
                zrun = zrun * g1 + z * g2;
                s1run = s1run * g1 + s1 * g2;
                mrun = MM;
                schrun = fmaxf(schrun, sch);
                __syncthreads();
            }
        }
        {
            int row = tid >> 1;
            if ((tid & 1) == 0 && r0 + row < cnt) {
                int b = ridx[row];
                float lz = mrun + __logf(zrun);
                out[(size_t)b * 3 + 0] = schrun - lz;
                out[(size_t)b * 3 + 2] = s1run / zrun - lz;
            }
        }
    } else {
        // ======== Critic [128 x 512 x 32], K-slice 16, 3-term, pipelined ========
        FragC acc[2];
        wmma::fill_fragment(acc[0], 0.f);
        wmma::fill_fragment(acc[1], 0.f);

        ldx8(xr, x, grow, 0, tid);
        stx8(sm, 0, xr, tid);
        ldx8(xr, x, grow, 1, tid);
        issue_cw(sm, 0, grp, 0, tid);
        CPC();

        for (int kc = 0; kc < 32; kc++) {
            int b = kc & 1;
            __syncthreads();  // (A)
            if (kc < 31) {
                issue_cw(sm, b ^ 1, grp, kc + 1, tid);
                CPC();
                CPW1();
            } else {
                CPW0();
            }
            __syncthreads();  // (B)
            const __nv_bfloat16* xh = (const __nv_bfloat16*)(sm + XS0 + b * 12288);
            const __nv_bfloat16* bh = (const __nv_bfloat16*)(sm + BT0 + b * 2560);
            FragA ah[2], al[2];
#pragma unroll
            for (int mi = 0; mi < 2; mi++) {
                wmma::load_matrix_sync(ah[mi], xh + (wm * 32 + mi * 16) * 24, 24);
                wmma::load_matrix_sync(al[mi], xh + 3072 + (wm * 32 + mi * 16) * 24, 24);
            }
            FragB fbh, fbl;
            wmma::load_matrix_sync(fbh, bh + wn * 16, 40);
            wmma::load_matrix_sync(fbl, bh + 640 + wn * 16, 40);
#pragma unroll
            for (int mi = 0; mi < 2; mi++) {
                wmma::mma_sync(acc[mi], ah[mi], fbh, acc[mi]);
                wmma::mma_sync(acc[mi], ah[mi], fbl, acc[mi]);
                wmma::mma_sync(acc[mi], al[mi], fbh, acc[mi]);
            }
            if (kc < 31) {
                stx8(sm, b ^ 1, xr, tid);
                if (kc < 30) ldx8(xr, x, grow, kc + 2, tid);
            }
        }
        __syncthreads();
#pragma unroll
        for (int mi = 0; mi < 2; mi++)
            wmma::store_matrix_sync(stg + (wm * 32 + mi * 16) * 36 + wn * 16, acc[mi], 36,
                                    wmma::mem_row_major);
        __syncthreads();
        {
            int row = tid >> 1, c0 = (tid & 1) * 16;
            const float4* hp = (const float4*)(stg + row * 36 + c0);
            const float4* b1p = (const float4*)((float*)(sm + CB1) + c0);
            const float4* w2p = (const float4*)((float*)(sm + CW2S) + c0);
            float sum = 0.f;
#pragma unroll
            for (int g = 0; g < 4; g++) {
                float4 h4 = hp[g], b4 = b1p[g], w4 = w2p[g];
                float h;
                h = h4.x + b4.x; sum += (h > 0.f ? h : 0.f) * w4.x;
                h = h4.y + b4.y; sum += (h > 0.f ? h : 0.f) * w4.y;
                h = h4.z + b4.z; sum += (h > 0.f ? h : 0.f) * w4.z;
                h = h4.w + b4.w; sum += (h > 0.f ? h : 0.f) * w4.w;
            }
            sum += __shfl_xor_sync(0xffffffffu, sum, 1);
            if ((tid & 1) == 0 && r0 + row < cnt)
                out[(size_t)ridx[row] * 3 + 1] = sum + Cb2[grp];
        }
    }
}

extern "C" void kernel_launch(void* const* d_in, const int* in_sizes, int n_in,
                              void* d_out, int out_size) {
    const float* x = (const float*)d_in[0];
    const int* commands = (const int*)d_in[1];
    const int* tasks = (const int*)d_in[2];
    const int* actions = (const int*)d_in[3];
    const float* A_W1 = (const float*)d_in[4];
    const float* A_b1 = (const float*)d_in[5];
    const float* A_W2 = (const float*)d_in[6];
    const float* A_b2 = (const float*)d_in[7];
    const float* C_W1 = (const float*)d_in[8];
    const float* C_b1 = (const float*)d_in[9];
    const float* C_W2 = (const float*)d_in[10];
    const float* C_b2 = (const float*)d_in[11];
    float* out = (float*)d_out;

    cudaFuncSetAttribute(fused_kernel, cudaFuncAttributeMaxDynamicSharedMemorySize,
                         SMEM_TOTAL);

    zero_kernel<<<1, 32>>>();
    route_kernel<<<Bn / 256, 256>>>(commands, tasks);
    int prep_elems = En * Fn * Hn + En * Hn * An + Tn * Fn * HCn;
    prep_kernel<<<(prep_elems + 255) / 256, 256>>>(A_W1, A_W2, C_W1);
    fused_kernel<<<dim3(NTILES_MAX, 1, 2), 256, SMEM_TOTAL>>>(
        x, actions, A_b1, A_b2, C_b1, C_W2, C_b2, out);
}

// round 14
// speedup vs baseline: 1.1672x; 1.1672x over previous
#include <cuda_runtime.h>
#include <cuda_bf16.h>
#include <mma.h>
#include <cstdint>

using namespace nvcuda;

#define Bn 32768
#define Fn 512
#define En 8
#define Hn 128
#define An 256
#define Tn 8
#define HCn 32
#define MT 64
#define NTILES_MAX 520

// ---- smem layout (bytes) ----
#define XS0   0         // 2 x 6144 x tiles ([64][24] bf16 hi + lo); doubles as f32 staging
#define BT0   12288     // weight tile buffers: 2 x 8704 ([16][136] bf16 hi at +0, lo at +4352)
#define HH    29696     // [64][136] bf16 (17408) -- h hi only (2-term GEMM2)
#define RIDX  47104
#define ACTS  47360
#define AB1   47616
#define AB2   48128
#define CB1   49152
#define CW2S  49280
#define SMEM_TOTAL 49408

// ---- device scratch ----
__device__ int g_acnt[En];
__device__ int g_ccnt[Tn];
__device__ int g_alist[En * Bn];
__device__ int g_clist[Tn * Bn];
__device__ __nv_bfloat16 g_aw1h[En * Fn * Hn];
__device__ __nv_bfloat16 g_aw1l[En * Fn * Hn];
__device__ __nv_bfloat16 g_aw2h[En * Hn * An];
__device__ __nv_bfloat16 g_aw2l[En * Hn * An];
__device__ __nv_bfloat16 g_cw1h[Tn * Fn * HCn];
__device__ __nv_bfloat16 g_cw1l[Tn * Fn * HCn];

typedef wmma::fragment<wmma::matrix_a, 16, 16, 16, __nv_bfloat16, wmma::row_major> FragA;
typedef wmma::fragment<wmma::matrix_b, 16, 16, 16, __nv_bfloat16, wmma::row_major> FragB;
typedef wmma::fragment<wmma::accumulator, 16, 16, 16, float> FragC;

// ---------------- routing ----------------
__global__ void zero_kernel() {
    int t = threadIdx.x;
    if (t < En) g_acnt[t] = 0;
    if (t < Tn) g_ccnt[t] = 0;
}

__global__ void route_kernel(const int* __restrict__ commands,
                             const int* __restrict__ tasks) {
    __shared__ int scA[En], scC[Tn], baseA[En], baseC[Tn];
    int tid = threadIdx.x;
    if (tid < En) scA[tid] = 0;
    if (tid < Tn) scC[tid] = 0;
    __syncthreads();
    int b = blockIdx.x * blockDim.x + tid;
    int e = commands[b];
    int pa = atomicAdd(&scA[e], 1);
    int t = tasks[b];
    int pc = atomicAdd(&scC[t], 1);
    __syncthreads();
    if (tid < En) baseA[tid] = atomicAdd(&g_acnt[tid], scA[tid]);
    if (tid < Tn) baseC[tid] = atomicAdd(&g_ccnt[tid], scC[tid]);
    __syncthreads();
    g_alist[e * Bn + baseA[e] + pa] = b;
    g_clist[t * Bn + baseC[t] + pc] = b;
}

// ---------------- weight split prep ----------------
__global__ void prep_kernel(const float* __restrict__ AW1, const float* __restrict__ AW2,
                            const float* __restrict__ CW1) {
    int i = blockIdx.x * 256 + threadIdx.x;
    if (i < En * Fn * Hn) {
        float f = AW1[i];
        __nv_bfloat16 h = __float2bfloat16(f);
        g_aw1h[i] = h;
        g_aw1l[i] = __float2bfloat16(f - __bfloat162float(h));
    } else if (i < En * Fn * Hn + En * Hn * An) {
        int j = i - En * Fn * Hn;
        float f = AW2[j];
        __nv_bfloat16 h = __float2bfloat16(f);
        g_aw2h[j] = h;
        g_aw2l[j] = __float2bfloat16(f - __bfloat162float(h));
    } else if (i < En * Fn * Hn + En * Hn * An + Tn * Fn * HCn) {
        int j = i - En * Fn * Hn - En * Hn * An;
        float f = CW1[j];
        __nv_bfloat16 h = __float2bfloat16(f);
        g_cw1h[j] = h;
        g_cw1l[j] = __float2bfloat16(f - __bfloat162float(h));
    }
}

// ---------------- helpers ----------------
__device__ __forceinline__ uint32_t pk(float a, float b) {
    __nv_bfloat162 t = __floats2bfloat162_rn(a, b);
    return *reinterpret_cast<uint32_t*>(&t);
}

__device__ __forceinline__ void split8(const float* f, uint4& hi, uint4& lo) {
    float fh[8], fl[8];
#pragma unroll
    for (int i = 0; i < 8; i++) {
        float h = __bfloat162float(__float2bfloat16(f[i]));
        fh[i] = h;
        fl[i] = f[i] - h;
    }
    hi = make_uint4(pk(fh[0], fh[1]), pk(fh[2], fh[3]), pk(fh[4], fh[5]), pk(fh[6], fh[7]));
    lo = make_uint4(pk(fl[0], fl[1]), pk(fl[2], fl[3]), pk(fl[4], fl[5]), pk(fl[6], fl[7]));
}

__device__ __forceinline__ uint32_t s2u(const void* p) {
    return (uint32_t)__cvta_generic_to_shared(p);
}
__device__ __forceinline__ void cpa(uint32_t d, const void* s) {
    asm volatile("cp.async.cg.shared.global [%0], [%1], 16;" :: "r"(d), "l"(s));
}
#define CPC() asm volatile("cp.async.commit_group;")
#define CPW1() asm volatile("cp.async.wait_group 1;")
#define CPW0() asm volatile("cp.async.wait_group 0;")

// raw mma helpers (m16n8k16 bf16, documented layouts)
__device__ __forceinline__ void ldsm4(uint32_t* r, uint32_t addr) {
    asm volatile("ldmatrix.sync.aligned.m8n8.x4.shared.b16 {%0,%1,%2,%3}, [%4];"
        : "=r"(r[0]), "=r"(r[1]), "=r"(r[2]), "=r"(r[3]) : "r"(addr));
}
__device__ __forceinline__ void ldsm2t(uint32_t* r, uint32_t addr) {
    asm volatile("ldmatrix.sync.aligned.m8n8.x2.trans.shared.b16 {%0,%1}, [%2];"
        : "=r"(r[0]), "=r"(r[1]) : "r"(addr));
}
__device__ __forceinline__ void mma16816(float* c, const uint32_t* a, const uint32_t* b) {
    asm volatile("mma.sync.aligned.m16n8k16.row.col.f32.bf16.bf16.f32 "
        "{%0,%1,%2,%3}, {%4,%5,%6,%7}, {%8,%9}, {%0,%1,%2,%3};"
        : "+f"(c[0]), "+f"(c[1]), "+f"(c[2]), "+f"(c[3])
        : "r"(a[0]), "r"(a[1]), "r"(a[2]), "r"(a[3]), "r"(b[0]), "r"(b[1]));
}

// load 8 fp32 of this thread's row slice (16-col slice, lane pair splits 8/8)
__device__ __forceinline__ void ldx8(float* r, const float* __restrict__ x, int grow,
                                     int kc, int tid) {
    const float4* s = (const float4*)(x + (size_t)grow * Fn + kc * 16 + (tid & 1) * 8);
    float4 v;
    v = s[0]; r[0] = v.x; r[1] = v.y; r[2] = v.z; r[3] = v.w;
    v = s[1]; r[4] = v.x; r[5] = v.y; r[6] = v.z; r[7] = v.w;
}

// split regs, store into XS buffer b ([64][24] bf16, hi at +0, lo at +3072)
__device__ __forceinline__ void stx8(unsigned char* sm, int b, const float* r, int tid) {
    uint4 hi, lo;
    split8(r, hi, lo);
    uint32_t a = (uint32_t)((tid >> 1) * 48 + (tid & 1) * 16);
    *(uint4*)(sm + XS0 + b * 6144 + a) = hi;
    *(uint4*)(sm + XS0 + b * 6144 + 3072 + a) = lo;
}

// W1 slice kc16 (16 k-rows x 128 cols) -> BT buffer (hi +0, lo +4352, stride 272B)
__device__ __forceinline__ void issue_w1(unsigned char* sm, int b, int grp, int kc16, int tid) {
    int k = tid >> 3, seg = tid & 7;
    size_t gb = (((size_t)grp * Fn + kc16 * 16 + k) << 7) + seg * 16;
    uint32_t d = s2u(sm + BT0) + b * 8704 + k * 272 + seg * 32;
    cpa(d, g_aw1h + gb);
    cpa(d + 16, g_aw1h + gb + 8);
    cpa(d + 4352, g_aw1l + gb);
    cpa(d + 4352 + 16, g_aw1l + gb + 8);
}
// W2 slice kcg (0..15): N-half = kcg>>3, local k-slice = kcg&7
__device__ __forceinline__ void issue_w2(unsigned char* sm, int b, int grp, int kcg, int tid) {
    int k = tid >> 3, seg = tid & 7;
    size_t gb = ((size_t)grp * Hn + (kcg & 7) * 16 + k) * An + (kcg >> 3) * 128 + seg * 16;
    uint32_t d = s2u(sm + BT0) + b * 8704 + k * 272 + seg * 32;
    cpa(d, g_aw2h + gb);
    cpa(d + 16, g_aw2h + gb + 8);
    cpa(d + 4352, g_aw2l + gb);
    cpa(d + 4352 + 16, g_aw2l + gb + 8);
}
// critic W1 slice (16 x 32), buffer b at BT0 + b*2560 (hi stride 80B, lo +1280)
__device__ __forceinline__ void issue_cw(unsigned char* sm, int b, int grp, int kc16, int tid) {
    if (tid < 64) {
        int row = tid >> 2, seg = tid & 3;
        size_t gb = ((size_t)grp * Fn + kc16 * 16 + row) * HCn + seg * 8;
        uint32_t d = s2u(sm + BT0) + b * 2560 + row * 80 + seg * 16;
        cpa(d, g_cw1h + gb);
        cpa(d + 1280, g_cw1l + gb);
    }
}

// ---------------- fused actor + critic ----------------
extern "C" __global__ void __launch_bounds__(128, 4)
fused_kernel(const float* __restrict__ x, const int* __restrict__ actions,
             const float* __restrict__ Ab1, const float* __restrict__ Ab2,
             const float* __restrict__ Cb1, const float* __restrict__ CW2,
             const float* __restrict__ Cb2, float* __restrict__ out) {
    extern __shared__ unsigned char sm[];
    int tid = threadIdx.x;
    int wid = tid >> 5;
    int wm = wid >> 1;
    int wn = wid & 1;
    int lane = tid & 31;
    bool is_actor = (blockIdx.z == 0);

    int grp = -1, local = blockIdx.x;
    const int* cnts = is_actor ? g_acnt : g_ccnt;
#pragma unroll
    for (int i = 0; i < En; i++) {
        int nt = (cnts[i] + MT - 1) / MT;
        if (grp < 0) {
            if (local < nt) grp = i;
            else local -= nt;
        }
    }
    if (grp < 0) return;
    int cnt = cnts[grp];
    int r0 = local * MT;

    int* ridx = (int*)(sm + RIDX);
    int* acts = (int*)(sm + ACTS);
    if (tid < MT) {
        int r = r0 + tid;
        const int* list = is_actor ? (g_alist + grp * Bn) : (g_clist + grp * Bn);
        int idx = (r < cnt) ? list[r] : -1;
        ridx[tid] = idx;
        if (is_actor) acts[tid] = (idx >= 0) ? actions[idx] : 0;
    }
    if (is_actor) {
        ((float*)(sm + AB1))[tid] = Ab1[grp * Hn + tid];
        ((float*)(sm + AB2))[tid] = Ab2[grp * An + tid];
        ((float*)(sm + AB2))[128 + tid] = Ab2[grp * An + 128 + tid];
    } else if (tid < HCn) {
        ((float*)(sm + CB1))[tid] = Cb1[grp * HCn + tid];
        ((float*)(sm + CW2S))[tid] = CW2[grp * HCn + tid];
    }
    __syncthreads();
    int rr = ridx[tid >> 1];
    int grow = rr < 0 ? 0 : rr;
    float xr[8];
    float* stg = (float*)(sm + XS0);  // f32 staging over dead XS region

    if (is_actor) {
        // ======== GEMM1: h = x @ W1 [64 x 512 x 128], K-slice 16, pipelined ====
        FragC acc[2][4];
#pragma unroll
        for (int mi = 0; mi < 2; mi++)
#pragma unroll
            for (int ni = 0; ni < 4; ni++) wmma::fill_fragment(acc[mi][ni], 0.f);

        ldx8(xr, x, grow, 0, tid);
        stx8(sm, 0, xr, tid);
        ldx8(xr, x, grow, 1, tid);
        issue_w1(sm, 0, grp, 0, tid);
        CPC();

        for (int kc = 0; kc < 32; kc++) {
            int b = kc & 1;
            __syncthreads();  // (A)
            if (kc < 31) issue_w1(sm, b ^ 1, grp, kc + 1, tid);
            else issue_w2(sm, 0, grp, 0, tid);  // prefetch GEMM2 kcg0 -> buf0
            CPC();
            CPW1();
            __syncthreads();  // (B)
            const __nv_bfloat16* xh = (const __nv_bfloat16*)(sm + XS0 + b * 6144);
            const __nv_bfloat16* bh = (const __nv_bfloat16*)(sm + BT0 + b * 8704);
            FragA ah[2], al[2];
#pragma unroll
            for (int mi = 0; mi < 2; mi++) {
                wmma::load_matrix_sync(ah[mi], xh + (wm * 32 + mi * 16) * 24, 24);
                wmma::load_matrix_sync(al[mi], xh + 1536 + (wm * 32 + mi * 16) * 24, 24);
            }
#pragma unroll
            for (int ni = 0; ni < 4; ni++) {
                FragB fbh, fbl;
                wmma::load_matrix_sync(fbh, bh + wn * 64 + ni * 16, 136);
                wmma::load_matrix_sync(fbl, bh + 2176 + wn * 64 + ni * 16, 136);
#pragma unroll
                for (int mi = 0; mi < 2; mi++) {
                    wmma::mma_sync(acc[mi][ni], ah[mi], fbh, acc[mi][ni]);
                    wmma::mma_sync(acc[mi][ni], ah[mi], fbl, acc[mi][ni]);
                    wmma::mma_sync(acc[mi][ni], al[mi], fbh, acc[mi][ni]);
                }
            }
            if (kc < 31) {
                stx8(sm, b ^ 1, xr, tid);
                if (kc < 30) ldx8(xr, x, grow, kc + 2, tid);
            }
        }

        // ---- GEMM1 epilogue: 4 passes of 32 cols via XS staging; h hi only ----
        __syncthreads();
#pragma unroll 1
        for (int p = 0; p < 4; p++) {
            if (wn == (p >> 1)) {
                int j0 = (p & 1) * 2;
#pragma unroll
                for (int mi = 0; mi < 2; mi++)
#pragma unroll
                    for (int j = 0; j < 2; j++)
                        wmma::store_matrix_sync(stg + (wm * 32 + mi * 16) * 36 + j * 16,
                                                acc[mi][j0 + j], 36, wmma::mem_row_major);
            }
            __syncthreads();
            int row = tid >> 1, cl = (tid & 1) * 16;
            const float* sp = stg + row * 36 + cl;
            const float* bp = (const float*)(sm + AB1) + p * 32 + cl;
#pragma unroll
            for (int g = 0; g < 2; g++) {
                float f[8];
#pragma unroll
                for (int i = 0; i < 8; i++) {
                    float h = sp[g * 8 + i] + bp[g * 8 + i];
                    f[i] = h > 0.f ? h : 0.f;
                }
                uint4 hi = make_uint4(pk(f[0], f[1]), pk(f[2], f[3]),
                                      pk(f[4], f[5]), pk(f[6], f[7]));
                *(uint4*)(sm + HH + (row * 136 + p * 32 + cl + g * 8) * 2) = hi;
            }
            __syncthreads();
        }

        // ======== GEMM2: raw mma m16n8k16, register softmax (2-term) ========
        uint32_t hhb = s2u(sm + HH);
        uint32_t btb = s2u(sm + BT0);
        // 4 row streams: s = mi*2 + u -> tile row wm*32 + mi*16 + (lane>>2) + u*8
        int rws[4], mact[4];
#pragma unroll
        for (int s = 0; s < 4; s++) {
            rws[s] = wm * 32 + (s >> 1) * 16 + (lane >> 2) + (s & 1) * 8;
            mact[s] = acts[rws[s]];
        }
        float mrun[4], zrun[4], s1run[4], schrun[4];
#pragma unroll
        for (int s = 0; s < 4; s++) {
            mrun[s] = -3e38f; zrun[s] = 0.f; s1run[s] = 0.f; schrun[s] = -3e38f;
        }

#pragma unroll 1
        for (int half = 0; half < 2; half++) {
            float a2[2][8][4];
#pragma unroll
            for (int mi = 0; mi < 2; mi++)
#pragma unroll
                for (int j = 0; j < 8; j++)
#pragma unroll
                    for (int k = 0; k < 4; k++) a2[mi][j][k] = 0.f;
#pragma unroll 1
            for (int kcl = 0; kcl < 8; kcl++) {
                int kcg = half * 8 + kcl;
                int b = kcg & 1;
                __syncthreads();  // (A)
                if (kcg < 15) {
                    issue_w2(sm, b ^ 1, grp, kcg + 1, tid);
                    CPC();
                    CPW1();
                } else {
                    CPW0();
                }
                __syncthreads();  // (B)
                uint32_t bt = btb + b * 8704;
#pragma unroll
                for (int mi = 0; mi < 2; mi++) {
                    uint32_t af[4];
                    uint32_t aaddr = hhb +
                        ((wm * 32 + mi * 16 + (lane & 15)) * 136 + kcl * 16 +
                         (lane >> 4) * 8) * 2;
                    ldsm4(af, aaddr);
#pragma unroll
                    for (int j = 0; j < 8; j++) {
                        uint32_t bhf[2], blf[2];
                        uint32_t baddr = bt + ((lane & 15) * 136 + wn * 64 + j * 8) * 2;
                        ldsm2t(bhf, baddr);
                        ldsm2t(blf, baddr + 4352);
                        mma16816(a2[mi][j], af, bhf);
                        mma16816(a2[mi][j], af, blf);
                    }
                }
            }
            // ---- register epilogue: bias + per-warp online softmax partials ----
            int cb = half * 128 + wn * 64 + 2 * (lane & 3);
            float mx[4] = {-3e38f, -3e38f, -3e38f, -3e38f};
#pragma unroll
            for (int mi = 0; mi < 2; mi++)
#pragma unroll
                for (int j = 0; j < 8; j++) {
                    float2 bb = *(const float2*)((const float*)(sm + AB2) + cb + j * 8);
                    a2[mi][j][0] += bb.x; a2[mi][j][1] += bb.y;
                    a2[mi][j][2] += bb.x; a2[mi][j][3] += bb.y;
                    mx[mi * 2] = fmaxf(mx[mi * 2], fmaxf(a2[mi][j][0], a2[mi][j][1]));
                    mx[mi * 2 + 1] = fmaxf(mx[mi * 2 + 1], fmaxf(a2[mi][j][2], a2[mi][j][3]));
                }
#pragma unroll
            for (int s = 0; s < 4; s++) {
                mx[s] = fmaxf(mx[s], __shfl_xor_sync(0xffffffffu, mx[s], 1));
                mx[s] = fmaxf(mx[s], __shfl_xor_sync(0xffffffffu, mx[s], 2));
            }
            float zz[4] = {0.f, 0.f, 0.f, 0.f}, ss[4] = {0.f, 0.f, 0.f, 0.f};
            float sc[4] = {-3e38f, -3e38f, -3e38f, -3e38f};
#pragma unroll
            for (int mi = 0; mi < 2; mi++)
#pragma unroll
                for (int j = 0; j < 8; j++) {
                    int c0 = cb + j * 8;
                    int s0 = mi * 2, s1i = mi * 2 + 1;
                    float v0 = a2[mi][j][0], v1 = a2[mi][j][1];
                    float v2 = a2[mi][j][2], v3 = a2[mi][j][3];
                    float p0 = __expf(v0 - mx[s0]), p1 = __expf(v1 - mx[s0]);
                    float p2 = __expf(v2 - mx[s1i]), p3 = __expf(v3 - mx[s1i]);
                    zz[s0] += p0 + p1;  ss[s0] += v0 * p0 + v1 * p1;
                    zz[s1i] += p2 + p3; ss[s1i] += v2 * p2 + v3 * p3;
                    if (c0 == mact[s0]) sc[s0] = v0;
                    if (c0 + 1 == mact[s0]) sc[s0] = v1;
                    if (c0 == mact[s1i]) sc[s1i] = v2;
                    if (c0 + 1 == mact[s1i]) sc[s1i] = v3;
                }
#pragma unroll
            for (int s = 0; s < 4; s++) {
                zz[s] += __shfl_xor_sync(0xffffffffu, zz[s], 1);
                zz[s] += __shfl_xor_sync(0xffffffffu, zz[s], 2);
                ss[s] += __shfl_xor_sync(0xffffffffu, ss[s], 1);
                ss[s] += __shfl_xor_sync(0xffffffffu, ss[s], 2);
                sc[s] = fmaxf(sc[s], __shfl_xor_sync(0xffffffffu, sc[s], 1));
                sc[s] = fmaxf(sc[s], __shfl_xor_sync(0xffffffffu, sc[s], 2));
                float M = fmaxf(mrun[s], mx[s]);
                float e1 = __expf(mrun[s] - M), e2 = __expf(mx[s] - M);
                zrun[s] = zrun[s] * e1 + zz[s] * e2;
                s1run[s] = s1run[s] * e1 + ss[s] * e2;
                mrun[s] = M;
                schrun[s] = fmaxf(schrun[s], sc[s]);
            }
        }
        // ---- cross-warp (wn) merge via stg: each row's stats live in BOTH wn
        // warps (each covering its 64-col slice of both halves). wn==1 publishes,
        // wn==0 merges (log-sum-exp combine) and is the sole output writer. ----
        __syncthreads();
        if (wn == 1 && (lane & 3) == 0) {
#pragma unroll
            for (int s = 0; s < 4; s++)
                *(float4*)(stg + rws[s] * 4) =
                    make_float4(mrun[s], zrun[s], s1run[s], schrun[s]);
        }
        __syncthreads();
        if (wn == 0 && (lane & 3) == 0) {
#pragma unroll
            for (int s = 0; s < 4; s++) {
                float4 o = *(const float4*)(stg + rws[s] * 4);
                float M = fmaxf(mrun[s], o.x);
                float e1 = __expf(mrun[s] - M), e2 = __expf(o.x - M);
                float z = zrun[s] * e1 + o.y * e2;
                float s1 = s1run[s] * e1 + o.z * e2;
                float sch = fmaxf(schrun[s], o.w);
                int rt = rws[s];
                if (r0 + rt < cnt) {
                    int b = ridx[rt];
                    float lz = M + __logf(z);
                    out[(size_t)b * 3 + 0] = sch - lz;
                    out[(size_t)b * 3 + 2] = s1 / z - lz;
                }
            }
        }
    } else {
        // ======== Critic [64 x 512 x 32], K-slice 16, 3-term, pipelined ========
        FragC acc[2];
        wmma::fill_fragment(acc[0], 0.f);
        wmma::fill_fragment(acc[1], 0.f);

        ldx8(xr, x, grow, 0, tid);
        stx8(sm, 0, xr, tid);
        ldx8(xr, x, grow, 1, tid);
        issue_cw(sm, 0, grp, 0, tid);
        CPC();

        for (int kc = 0; kc < 32; kc++) {
            int b = kc & 1;
            __syncthreads();  // (A)
            if (kc < 31) {
                issue_cw(sm, b ^ 1, grp, kc + 1, tid);
                CPC();
                CPW1();
            } else {
                CPW0();
            }
            __syncthreads();  // (B)
            const __nv_bfloat16* xh = (const __nv_bfloat16*)(sm + XS0 + b * 6144);
            const __nv_bfloat16* bh = (const __nv_bfloat16*)(sm + BT0 + b * 2560);
            FragA ah[2], al[2];
#pragma unroll
            for (int mi = 0; mi < 2; mi++) {
                wmma::load_matrix_sync(ah[mi], xh + (wm * 32 + mi * 16) * 24, 24);
                wmma::load_matrix_sync(al[mi], xh + 1536 + (wm * 32 + mi * 16) * 24, 24);
            }
            FragB fbh, fbl;
            wmma::load_matrix_sync(fbh, bh + wn * 16, 40);
            wmma::load_matrix_sync(fbl, bh + 640 + wn * 16, 40);
#pragma unroll
            for (int mi = 0; mi < 2; mi++) {
                wmma::mma_sync(acc[mi], ah[mi], fbh, acc[mi]);
                wmma::mma_sync(acc[mi], ah[mi], fbl, acc[mi]);
                wmma::mma_sync(acc[mi], al[mi], fbh, acc[mi]);
            }
            if (kc < 31) {
                stx8(sm, b ^ 1, xr, tid);
                if (kc < 30) ldx8(xr, x, grow, kc + 2, tid);
            }
        }
        __syncthreads();
#pragma unroll
        for (int mi = 0; mi < 2; mi++)
            wmma::store_matrix_sync(stg + (wm * 32 + mi * 16) * 36 + wn * 16, acc[mi], 36,
                                    wmma::mem_row_major);
        __syncthreads();
        {
            int row = tid >> 1, c0 = (tid & 1) * 16;
            const float4* hp = (const float4*)(stg + row * 36 + c0);
            const float4* b1p = (const float4*)((float*)(sm + CB1) + c0);
            const float4* w2p = (const float4*)((float*)(sm + CW2S) + c0);
            float sum = 0.f;
#pragma unroll
            for (int g = 0; g < 4; g++) {
                float4 h4 = hp[g], b4 = b1p[g], w4 = w2p[g];
                float h;
                h = h4.x + b4.x; sum += (h > 0.f ? h : 0.f) * w4.x;
                h = h4.y + b4.y; sum += (h > 0.f ? h : 0.f) * w4.y;
                h = h4.z + b4.z; sum += (h > 0.f ? h : 0.f) * w4.z;
                h = h4.w + b4.w; sum += (h > 0.f ? h : 0.f) * w4.w;
            }
            sum += __shfl_xor_sync(0xffffffffu, sum, 1);
            if ((tid & 1) == 0 && r0 + row < cnt)
                out[(size_t)ridx[row] * 3 + 1] = sum + Cb2[grp];
        }
    }
}

extern "C" void kernel_launch(void* const* d_in, const int* in_sizes, int n_in,
                              void* d_out, int out_size) {
    const float* x = (const float*)d_in[0];
    const int* commands = (const int*)d_in[1];
    const int* tasks = (const int*)d_in[2];
    const int* actions = (const int*)d_in[3];
    const float* A_W1 = (const float*)d_in[4];
    const float* A_b1 = (const float*)d_in[5];
    const float* A_W2 = (const float*)d_in[6];
    const float* A_b2 = (const float*)d_in[7];
    const float* C_W1 = (const float*)d_in[8];
    const float* C_b1 = (const float*)d_in[9];
    const float* C_W2 = (const float*)d_in[10];
    const float* C_b2 = (const float*)d_in[11];
    float* out = (float*)d_out;

    cudaFuncSetAttribute(fused_kernel, cudaFuncAttributeMaxDynamicSharedMemorySize,
                         SMEM_TOTAL);

    zero_kernel<<<1, 32>>>();
    route_kernel<<<Bn / 256, 256>>>(commands, tasks);
    int prep_elems = En * Fn * Hn + En * Hn * An + Tn * Fn * HCn;
    prep_kernel<<<(prep_elems + 255) / 256, 256>>>(A_W1, A_W2, C_W1);
    fused_kernel<<<dim3(NTILES_MAX, 1, 2), 128, SMEM_TOTAL>>>(
        x, actions, A_b1, A_b2, C_b1, C_W2, C_b2, out);
}

// round 15
// speedup vs baseline: 1.3798x; 1.1821x over previous
#include <cuda_runtime.h>
#include <cuda_bf16.h>
#include <mma.h>
#include <cstdint>

using namespace nvcuda;

#define Bn 32768
#define Fn 512
#define En 8
#define Hn 128
#define An 256
#define Tn 8
#define HCn 32
#define MT 64
#define NTILES_MAX 520

// ---- smem layout (bytes) ----
#define XS0   0         // 2 x 6144 x tiles ([64][24] bf16 hi + lo); doubles as f32 staging
#define BT0   12288     // weight tile buffers: 2 x 8704 ([16][136] bf16 hi at +0, lo at +4352)
#define HH    29696     // [64][136] bf16 (17408) -- h hi only (2-term GEMM2)
#define RIDX  47104
#define ACTS  47360
#define AB1   47616
#define AB2   48128
#define CB1   49152
#define CW2S  49280
#define SMEM_TOTAL 49408

// ---- device scratch ----
__device__ int g_acnt[En];
__device__ int g_ccnt[Tn];
__device__ int g_alist[En * Bn];
__device__ int g_clist[Tn * Bn];
__device__ __nv_bfloat16 g_aw1h[En * Fn * Hn];
__device__ __nv_bfloat16 g_aw1l[En * Fn * Hn];
__device__ __nv_bfloat16 g_aw2h[En * Hn * An];
__device__ __nv_bfloat16 g_aw2l[En * Hn * An];
__device__ __nv_bfloat16 g_cw1h[Tn * Fn * HCn];
__device__ __nv_bfloat16 g_cw1l[Tn * Fn * HCn];

typedef wmma::fragment<wmma::matrix_a, 16, 16, 16, __nv_bfloat16, wmma::row_major> FragA;
typedef wmma::fragment<wmma::matrix_b, 16, 16, 16, __nv_bfloat16, wmma::row_major> FragB;
typedef wmma::fragment<wmma::accumulator, 16, 16, 16, float> FragC;

// ---------------- routing ----------------
__global__ void zero_kernel() {
    int t = threadIdx.x;
    if (t < En) g_acnt[t] = 0;
    if (t < Tn) g_ccnt[t] = 0;
}

__global__ void route_kernel(const int* __restrict__ commands,
                             const int* __restrict__ tasks) {
    __shared__ int scA[En], scC[Tn], baseA[En], baseC[Tn];
    int tid = threadIdx.x;
    if (tid < En) scA[tid] = 0;
    if (tid < Tn) scC[tid] = 0;
    __syncthreads();
    int b = blockIdx.x * blockDim.x + tid;
    int e = commands[b];
    int pa = atomicAdd(&scA[e], 1);
    int t = tasks[b];
    int pc = atomicAdd(&scC[t], 1);
    __syncthreads();
    if (tid < En) baseA[tid] = atomicAdd(&g_acnt[tid], scA[tid]);
    if (tid < Tn) baseC[tid] = atomicAdd(&g_ccnt[tid], scC[tid]);
    __syncthreads();
    g_alist[e * Bn + baseA[e] + pa] = b;
    g_clist[t * Bn + baseC[t] + pc] = b;
}

// ---------------- weight split prep ----------------
__global__ void prep_kernel(const float* __restrict__ AW1, const float* __restrict__ AW2,
                            const float* __restrict__ CW1) {
    int i = blockIdx.x * 256 + threadIdx.x;
    if (i < En * Fn * Hn) {
        float f = AW1[i];
        __nv_bfloat16 h = __float2bfloat16(f);
        g_aw1h[i] = h;
        g_aw1l[i] = __float2bfloat16(f - __bfloat162float(h));
    } else if (i < En * Fn * Hn + En * Hn * An) {
        int j = i - En * Fn * Hn;
        float f = AW2[j];
        __nv_bfloat16 h = __float2bfloat16(f);
        g_aw2h[j] = h;
        g_aw2l[j] = __float2bfloat16(f - __bfloat162float(h));
    } else if (i < En * Fn * Hn + En * Hn * An + Tn * Fn * HCn) {
        int j = i - En * Fn * Hn - En * Hn * An;
        float f = CW1[j];
        __nv_bfloat16 h = __float2bfloat16(f);
        g_cw1h[j] = h;
        g_cw1l[j] = __float2bfloat16(f - __bfloat162float(h));
    }
}

// ---------------- helpers ----------------
__device__ __forceinline__ uint32_t pk(float a, float b) {
    __nv_bfloat162 t = __floats2bfloat162_rn(a, b);
    return *reinterpret_cast<uint32_t*>(&t);
}

__device__ __forceinline__ void split8(const float* f, uint4& hi, uint4& lo) {
    float fh[8], fl[8];
#pragma unroll
    for (int i = 0; i < 8; i++) {
        float h = __bfloat162float(__float2bfloat16(f[i]));
        fh[i] = h;
        fl[i] = f[i] - h;
    }
    hi = make_uint4(pk(fh[0], fh[1]), pk(fh[2], fh[3]), pk(fh[4], fh[5]), pk(fh[6], fh[7]));
    lo = make_uint4(pk(fl[0], fl[1]), pk(fl[2], fl[3]), pk(fl[4], fl[5]), pk(fl[6], fl[7]));
}

__device__ __forceinline__ uint32_t s2u(const void* p) {
    return (uint32_t)__cvta_generic_to_shared(p);
}
__device__ __forceinline__ void cpa(uint32_t d, const void* s) {
    asm volatile("cp.async.cg.shared.global [%0], [%1], 16;" :: "r"(d), "l"(s));
}
#define CPC() asm volatile("cp.async.commit_group;")
#define CPW1() asm volatile("cp.async.wait_group 1;")
#define CPW0() asm volatile("cp.async.wait_group 0;")

// raw mma helpers (m16n8k16 bf16, documented layouts)
__device__ __forceinline__ void ldsm4(uint32_t* r, uint32_t addr) {
    asm volatile("ldmatrix.sync.aligned.m8n8.x4.shared.b16 {%0,%1,%2,%3}, [%4];"
        : "=r"(r[0]), "=r"(r[1]), "=r"(r[2]), "=r"(r[3]) : "r"(addr));
}
__device__ __forceinline__ void ldsm2t(uint32_t* r, uint32_t addr) {
    asm volatile("ldmatrix.sync.aligned.m8n8.x2.trans.shared.b16 {%0,%1}, [%2];"
        : "=r"(r[0]), "=r"(r[1]) : "r"(addr));
}
__device__ __forceinline__ void mma16816(float* c, const uint32_t* a, const uint32_t* b) {
    asm volatile("mma.sync.aligned.m16n8k16.row.col.f32.bf16.bf16.f32 "
        "{%0,%1,%2,%3}, {%4,%5,%6,%7}, {%8,%9}, {%0,%1,%2,%3};"
        : "+f"(c[0]), "+f"(c[1]), "+f"(c[2]), "+f"(c[3])
        : "r"(a[0]), "r"(a[1]), "r"(a[2]), "r"(a[3]), "r"(b[0]), "r"(b[1]));
}

// load 8 fp32 of this thread's row slice (16-col slice, lane pair splits 8/8)
__device__ __forceinline__ void ldx8(float* r, const float* __restrict__ x, int grow,
                                     int kc, int tid) {
    const float4* s = (const float4*)(x + (size_t)grow * Fn + kc * 16 + (tid & 1) * 8);
    float4 v;
    v = s[0]; r[0] = v.x; r[1] = v.y; r[2] = v.z; r[3] = v.w;
    v = s[1]; r[4] = v.x; r[5] = v.y; r[6] = v.z; r[7] = v.w;
}

// split regs, store into XS buffer b ([64][24] bf16, hi at +0, lo at +3072)
__device__ __forceinline__ void stx8(unsigned char* sm, int b, const float* r, int tid) {
    uint4 hi, lo;
    split8(r, hi, lo);
    uint32_t a = (uint32_t)((tid >> 1) * 48 + (tid & 1) * 16);
    *(uint4*)(sm + XS0 + b * 6144 + a) = hi;
    *(uint4*)(sm + XS0 + b * 6144 + 3072 + a) = lo;
}

// W1 slice kc16 (16 k-rows x 128 cols) -> BT buffer (hi +0, lo +4352, stride 272B)
__device__ __forceinline__ void issue_w1(unsigned char* sm, int b, int grp, int kc16, int tid) {
    int k = tid >> 3, seg = tid & 7;
    size_t gb = (((size_t)grp * Fn + kc16 * 16 + k) << 7) + seg * 16;
    uint32_t d = s2u(sm + BT0) + b * 8704 + k * 272 + seg * 32;
    cpa(d, g_aw1h + gb);
    cpa(d + 16, g_aw1h + gb + 8);
    cpa(d + 4352, g_aw1l + gb);
    cpa(d + 4352 + 16, g_aw1l + gb + 8);
}
// W2 slice kcg (0..15): N-half = kcg>>3, local k-slice = kcg&7
__device__ __forceinline__ void issue_w2(unsigned char* sm, int b, int grp, int kcg, int tid) {
    int k = tid >> 3, seg = tid & 7;
    size_t gb = ((size_t)grp * Hn + (kcg & 7) * 16 + k) * An + (kcg >> 3) * 128 + seg * 16;
    uint32_t d = s2u(sm + BT0) + b * 8704 + k * 272 + seg * 32;
    cpa(d, g_aw2h + gb);
    cpa(d + 16, g_aw2h + gb + 8);
    cpa(d + 4352, g_aw2l + gb);
    cpa(d + 4352 + 16, g_aw2l + gb + 8);
}
// critic W1 slice (16 x 32), buffer b at BT0 + b*2560 (hi stride 80B, lo +1280)
__device__ __forceinline__ void issue_cw(unsigned char* sm, int b, int grp, int kc16, int tid) {
    if (tid < 64) {
        int row = tid >> 2, seg = tid & 3;
        size_t gb = ((size_t)grp * Fn + kc16 * 16 + row) * HCn + seg * 8;
        uint32_t d = s2u(sm + BT0) + b * 2560 + row * 80 + seg * 16;
        cpa(d, g_cw1h + gb);
        cpa(d + 1280, g_cw1l + gb);
    }
}

// ---------------- fused actor + critic ----------------
extern "C" __global__ void __launch_bounds__(128, 4)
fused_kernel(const float* __restrict__ x, const int* __restrict__ actions,
             const float* __restrict__ Ab1, const float* __restrict__ Ab2,
             const float* __restrict__ Cb1, const float* __restrict__ CW2,
             const float* __restrict__ Cb2, float* __restrict__ out) {
    extern __shared__ unsigned char sm[];
    int tid = threadIdx.x;
    int wid = tid >> 5;
    int wm = wid >> 1;
    int wn = wid & 1;
    int lane = tid & 31;
    bool is_actor = (blockIdx.z == 0);

    int grp = -1, local = blockIdx.x;
    const int* cnts = is_actor ? g_acnt : g_ccnt;
#pragma unroll
    for (int i = 0; i < En; i++) {
        int nt = (cnts[i] + MT - 1) / MT;
        if (grp < 0) {
            if (local < nt) grp = i;
            else local -= nt;
        }
    }
    if (grp < 0) return;
    int cnt = cnts[grp];
    int r0 = local * MT;

    int* ridx = (int*)(sm + RIDX);
    int* acts = (int*)(sm + ACTS);
    if (tid < MT) {
        int r = r0 + tid;
        const int* list = is_actor ? (g_alist + grp * Bn) : (g_clist + grp * Bn);
        int idx = (r < cnt) ? list[r] : -1;
        ridx[tid] = idx;
        if (is_actor) acts[tid] = (idx >= 0) ? actions[idx] : 0;
    }
    if (is_actor) {
        ((float*)(sm + AB1))[tid] = Ab1[grp * Hn + tid];
        ((float*)(sm + AB2))[tid] = Ab2[grp * An + tid];
        ((float*)(sm + AB2))[128 + tid] = Ab2[grp * An + 128 + tid];
    } else if (tid < HCn) {
        ((float*)(sm + CB1))[tid] = Cb1[grp * HCn + tid];
        ((float*)(sm + CW2S))[tid] = CW2[grp * HCn + tid];
    }
    __syncthreads();
    int rr = ridx[tid >> 1];
    int grow = rr < 0 ? 0 : rr;
    float xr[8];
    float* stg = (float*)(sm + XS0);  // f32 staging over dead XS region (critic + merge)

    if (is_actor) {
        uint32_t hhb = s2u(sm + HH);
        uint32_t btb = s2u(sm + BT0);
        uint32_t xsb = s2u(sm + XS0);
        // accumulators: [mi][j][4], rows wm*32+mi*16+(lane>>2)+(k>>1)*8,
        // cols wn*64+j*8+2*(lane&3)+(k&1)
        float accr[2][8][4];
#pragma unroll
        for (int mi = 0; mi < 2; mi++)
#pragma unroll
            for (int j = 0; j < 8; j++)
#pragma unroll
                for (int k = 0; k < 4; k++) accr[mi][j][k] = 0.f;

        // ======== GEMM1: h = x @ W1 [64 x 512 x 128], raw mma, pipelined ====
        ldx8(xr, x, grow, 0, tid);
        stx8(sm, 0, xr, tid);
        ldx8(xr, x, grow, 1, tid);
        issue_w1(sm, 0, grp, 0, tid);
        CPC();

        for (int kc = 0; kc < 32; kc++) {
            int b = kc & 1;
            __syncthreads();  // (A)
            if (kc < 31) issue_w1(sm, b ^ 1, grp, kc + 1, tid);
            else issue_w2(sm, 0, grp, 0, tid);  // prefetch GEMM2 kcg0 -> buf0
            CPC();
            CPW1();
            __syncthreads();  // (B)
            uint32_t xs = xsb + b * 6144;
            uint32_t bt = btb + b * 8704;
            uint32_t ah[2][4], al[2][4];
#pragma unroll
            for (int mi = 0; mi < 2; mi++) {
                uint32_t aaddr = xs +
                    ((wm * 32 + mi * 16 + (lane & 15)) * 24 + (lane >> 4) * 8) * 2;
                ldsm4(ah[mi], aaddr);
                ldsm4(al[mi], aaddr + 3072);
            }
#pragma unroll
            for (int j = 0; j < 8; j++) {
                uint32_t bhf[2], blf[2];
                uint32_t baddr = bt + ((lane & 15) * 136 + wn * 64 + j * 8) * 2;
                ldsm2t(bhf, baddr);
                ldsm2t(blf, baddr + 4352);
#pragma unroll
                for (int mi = 0; mi < 2; mi++) {
                    mma16816(accr[mi][j], ah[mi], bhf);
                    mma16816(accr[mi][j], ah[mi], blf);
                    mma16816(accr[mi][j], al[mi], bhf);
                }
            }
            if (kc < 31) {
                stx8(sm, b ^ 1, xr, tid);
                if (kc < 30) ldx8(xr, x, grow, kc + 2, tid);
            }
        }

        // ---- GEMM1 epilogue: register bias+relu+bf16, direct STS to HH ----
        // (ordered before GEMM2's ldsm by GEMM2's (A)+(B) barriers)
        {
            int c0 = wn * 64 + 2 * (lane & 3);
            int rbase = wm * 32 + (lane >> 2);
#pragma unroll
            for (int mi = 0; mi < 2; mi++)
#pragma unroll
                for (int j = 0; j < 8; j++) {
                    float2 bb = *(const float2*)((const float*)(sm + AB1) + c0 + j * 8);
                    float v0 = accr[mi][j][0] + bb.x, v1 = accr[mi][j][1] + bb.y;
                    float v2 = accr[mi][j][2] + bb.x, v3 = accr[mi][j][3] + bb.y;
                    v0 = v0 > 0.f ? v0 : 0.f; v1 = v1 > 0.f ? v1 : 0.f;
                    v2 = v2 > 0.f ? v2 : 0.f; v3 = v3 > 0.f ? v3 : 0.f;
                    int row0 = rbase + mi * 16;
                    *(uint32_t*)(sm + HH + (row0 * 136 + c0 + j * 8) * 2) = pk(v0, v1);
                    *(uint32_t*)(sm + HH + ((row0 + 8) * 136 + c0 + j * 8) * 2) = pk(v2, v3);
                }
        }

        // ======== GEMM2: raw mma, register softmax (2-term) ========
        int rws[4], mact[4];
#pragma unroll
        for (int s = 0; s < 4; s++) {
            rws[s] = wm * 32 + (s >> 1) * 16 + (lane >> 2) + (s & 1) * 8;
            mact[s] = acts[rws[s]];
        }
        float mrun[4], zrun[4], s1run[4], schrun[4];
#pragma unroll
        for (int s = 0; s < 4; s++) {
            mrun[s] = -3e38f; zrun[s] = 0.f; s1run[s] = 0.f; schrun[s] = -3e38f;
        }

#pragma unroll 1
        for (int half = 0; half < 2; half++) {
#pragma unroll
            for (int mi = 0; mi < 2; mi++)
#pragma unroll
                for (int j = 0; j < 8; j++)
#pragma unroll
                    for (int k = 0; k < 4; k++) accr[mi][j][k] = 0.f;
#pragma unroll 1
            for (int kcl = 0; kcl < 8; kcl++) {
                int kcg = half * 8 + kcl;
                int b = kcg & 1;
                __syncthreads();  // (A)
                if (kcg < 15) {
                    issue_w2(sm, b ^ 1, grp, kcg + 1, tid);
                    CPC();
                    CPW1();
                } else {
                    CPW0();
                }
                __syncthreads();  // (B)
                uint32_t bt = btb + b * 8704;
                uint32_t af[2][4];
#pragma unroll
                for (int mi = 0; mi < 2; mi++) {
                    uint32_t aaddr = hhb +
                        ((wm * 32 + mi * 16 + (lane & 15)) * 136 + kcl * 16 +
                         (lane >> 4) * 8) * 2;
                    ldsm4(af[mi], aaddr);
                }
#pragma unroll
                for (int j = 0; j < 8; j++) {
                    uint32_t bhf[2], blf[2];
                    uint32_t baddr = bt + ((lane & 15) * 136 + wn * 64 + j * 8) * 2;
                    ldsm2t(bhf, baddr);
                    ldsm2t(blf, baddr + 4352);
#pragma unroll
                    for (int mi = 0; mi < 2; mi++) {
                        mma16816(accr[mi][j], af[mi], bhf);
                        mma16816(accr[mi][j], af[mi], blf);
                    }
                }
            }
            // ---- register epilogue: bias + per-warp online softmax partials ----
            int cb = half * 128 + wn * 64 + 2 * (lane & 3);
            float mx[4] = {-3e38f, -3e38f, -3e38f, -3e38f};
#pragma unroll
            for (int mi = 0; mi < 2; mi++)
#pragma unroll
                for (int j = 0; j < 8; j++) {
                    float2 bb = *(const float2*)((const float*)(sm + AB2) + cb + j * 8);
                    accr[mi][j][0] += bb.x; accr[mi][j][1] += bb.y;
                    accr[mi][j][2] += bb.x; accr[mi][j][3] += bb.y;
                    mx[mi * 2] = fmaxf(mx[mi * 2], fmaxf(accr[mi][j][0], accr[mi][j][1]));
                    mx[mi * 2 + 1] = fmaxf(mx[mi * 2 + 1], fmaxf(accr[mi][j][2], accr[mi][j][3]));
                }
#pragma unroll
            for (int s = 0; s < 4; s++) {
                mx[s] = fmaxf(mx[s], __shfl_xor_sync(0xffffffffu, mx[s], 1));
                mx[s] = fmaxf(mx[s], __shfl_xor_sync(0xffffffffu, mx[s], 2));
            }
            float zz[4] = {0.f, 0.f, 0.f, 0.f}, ss[4] = {0.f, 0.f, 0.f, 0.f};
            float sc[4] = {-3e38f, -3e38f, -3e38f, -3e38f};
#pragma unroll
            for (int mi = 0; mi < 2; mi++)
#pragma unroll
                for (int j = 0; j < 8; j++) {
                    int c0 = cb + j * 8;
                    int s0 = mi * 2, s1i = mi * 2 + 1;
                    float v0 = accr[mi][j][0], v1 = accr[mi][j][1];
                    float v2 = accr[mi][j][2], v3 = accr[mi][j][3];
                    float p0 = __expf(v0 - mx[s0]), p1 = __expf(v1 - mx[s0]);
                    float p2 = __expf(v2 - mx[s1i]), p3 = __expf(v3 - mx[s1i]);
                    zz[s0] += p0 + p1;  ss[s0] += v0 * p0 + v1 * p1;
                    zz[s1i] += p2 + p3; ss[s1i] += v2 * p2 + v3 * p3;
                    if (c0 == mact[s0]) sc[s0] = v0;
                    if (c0 + 1 == mact[s0]) sc[s0] = v1;
                    if (c0 == mact[s1i]) sc[s1i] = v2;
                    if (c0 + 1 == mact[s1i]) sc[s1i] = v3;
                }
#pragma unroll
            for (int s = 0; s < 4; s++) {
                zz[s] += __shfl_xor_sync(0xffffffffu, zz[s], 1);
                zz[s] += __shfl_xor_sync(0xffffffffu, zz[s], 2);
                ss[s] += __shfl_xor_sync(0xffffffffu, ss[s], 1);
                ss[s] += __shfl_xor_sync(0xffffffffu, ss[s], 2);
                sc[s] = fmaxf(sc[s], __shfl_xor_sync(0xffffffffu, sc[s], 1));
                sc[s] = fmaxf(sc[s], __shfl_xor_sync(0xffffffffu, sc[s], 2));
                float M = fmaxf(mrun[s], mx[s]);
                float e1 = __expf(mrun[s] - M), e2 = __expf(mx[s] - M);
                zrun[s] = zrun[s] * e1 + zz[s] * e2;
                s1run[s] = s1run[s] * e1 + ss[s] * e2;
                mrun[s] = M;
                schrun[s] = fmaxf(schrun[s], sc[s]);
            }
        }
        // ---- cross-warp (wn) merge via stg; wn==0 writes output ----
        __syncthreads();
        if (wn == 1 && (lane & 3) == 0) {
#pragma unroll
            for (int s = 0; s < 4; s++)
                *(float4*)(stg + rws[s] * 4) =
                    make_float4(mrun[s], zrun[s], s1run[s], schrun[s]);
        }
        __syncthreads();
        if (wn == 0 && (lane & 3) == 0) {
#pragma unroll
            for (int s = 0; s < 4; s++) {
                float4 o = *(const float4*)(stg + rws[s] * 4);
                float M = fmaxf(mrun[s], o.x);
                float e1 = __expf(mrun[s] - M), e2 = __expf(o.x - M);
                float z = zrun[s] * e1 + o.y * e2;
                float s1 = s1run[s] * e1 + o.z * e2;
                float sch = fmaxf(schrun[s], o.w);
                int rt = rws[s];
                if (r0 + rt < cnt) {
                    int b = ridx[rt];
                    float lz = M + __logf(z);
                    out[(size_t)b * 3 + 0] = sch - lz;
                    out[(size_t)b * 3 + 2] = s1 / z - lz;
                }
            }
        }
    } else {
        // ======== Critic [64 x 512 x 32], K-slice 16, 3-term, pipelined ========
        FragC acc[2];
        wmma::fill_fragment(acc[0], 0.f);
        wmma::fill_fragment(acc[1], 0.f);

        ldx8(xr, x, grow, 0, tid);
        stx8(sm, 0, xr, tid);
        ldx8(xr, x, grow, 1, tid);
        issue_cw(sm, 0, grp, 0, tid);
        CPC();

        for (int kc = 0; kc < 32; kc++) {
            int b = kc & 1;
            __syncthreads();  // (A)
            if (kc < 31) {
                issue_cw(sm, b ^ 1, grp, kc + 1, tid);
                CPC();
                CPW1();
            } else {
                CPW0();
            }
            __syncthreads();  // (B)
            const __nv_bfloat16* xh = (const __nv_bfloat16*)(sm + XS0 + b * 6144);
            const __nv_bfloat16* bh = (const __nv_bfloat16*)(sm + BT0 + b * 2560);
            FragA ah[2], al[2];
#pragma unroll
            for (int mi = 0; mi < 2; mi++) {
                wmma::load_matrix_sync(ah[mi], xh + (wm * 32 + mi * 16) * 24, 24);
                wmma::load_matrix_sync(al[mi], xh + 1536 + (wm * 32 + mi * 16) * 24, 24);
            }
            FragB fbh, fbl;
            wmma::load_matrix_sync(fbh, bh + wn * 16, 40);
            wmma::load_matrix_sync(fbl, bh + 640 + wn * 16, 40);
#pragma unroll
            for (int mi = 0; mi < 2; mi++) {
                wmma::mma_sync(acc[mi], ah[mi], fbh, acc[mi]);
                wmma::mma_sync(acc[mi], ah[mi], fbl, acc[mi]);
                wmma::mma_sync(acc[mi], al[mi], fbh, acc[mi]);
            }
            if (kc < 31) {
                stx8(sm, b ^ 1, xr, tid);
                if (kc < 30) ldx8(xr, x, grow, kc + 2, tid);
            }
        }
        __syncthreads();
#pragma unroll
        for (int mi = 0; mi < 2; mi++)
            wmma::store_matrix_sync(stg + (wm * 32 + mi * 16) * 36 + wn * 16, acc[mi], 36,
                                    wmma::mem_row_major);
        __syncthreads();
        {
            int row = tid >> 1, c0 = (tid & 1) * 16;
            const float4* hp = (const float4*)(stg + row * 36 + c0);
            const float4* b1p = (const float4*)((float*)(sm + CB1) + c0);
            const float4* w2p = (const float4*)((float*)(sm + CW2S) + c0);
            float sum = 0.f;
#pragma unroll
            for (int g = 0; g < 4; g++) {
                float4 h4 = hp[g], b4 = b1p[g], w4 = w2p[g];
                float h;
                h = h4.x + b4.x; sum += (h > 0.f ? h : 0.f) * w4.x;
                h = h4.y + b4.y; sum += (h > 0.f ? h : 0.f) * w4.y;
                h = h4.z + b4.z; sum += (h > 0.f ? h : 0.f) * w4.z;
                h = h4.w + b4.w; sum += (h > 0.f ? h : 0.f) * w4.w;
            }
            sum += __shfl_xor_sync(0xffffffffu, sum, 1);
            if ((tid & 1) == 0 && r0 + row < cnt)
                out[(size_t)ridx[row] * 3 + 1] = sum + Cb2[grp];
        }
    }
}

extern "C" void kernel_launch(void* const* d_in, const int* in_sizes, int n_in,
                              void* d_out, int out_size) {
    const float* x = (const float*)d_in[0];
    const int* commands = (const int*)d_in[1];
    const int* tasks = (const int*)d_in[2];
    const int* actions = (const int*)d_in[3];
    const float* A_W1 = (const float*)d_in[4];
    const float* A_b1 = (const float*)d_in[5];
    const float* A_W2 = (const float*)d_in[6];
    const float* A_b2 = (const float*)d_in[7];
    const float* C_W1 = (const float*)d_in[8];
    const float* C_b1 = (const float*)d_in[9];
    const float* C_W2 = (const float*)d_in[10];
    const float* C_b2 = (const float*)d_in[11];
    float* out = (float*)d_out;

    cudaFuncSetAttribute(fused_kernel, cudaFuncAttributeMaxDynamicSharedMemorySize,
                         SMEM_TOTAL);

    zero_kernel<<<1, 32>>>();
    route_kernel<<<Bn / 256, 256>>>(commands, tasks);
    int prep_elems = En * Fn * Hn + En * Hn * An + Tn * Fn * HCn;
    prep_kernel<<<(prep_elems + 255) / 256, 256>>>(A_W1, A_W2, C_W1);
    fused_kernel<<<dim3(NTILES_MAX, 1, 2), 128, SMEM_TOTAL>>>(
        x, actions, A_b1, A_b2, C_b1, C_W2, C_b2, out);
}

// round 16
// speedup vs baseline: 1.4679x; 1.0639x over previous
#include <cuda_runtime.h>
#include <cuda_bf16.h>
#include <mma.h>
#include <cstdint>

using namespace nvcuda;

#define Bn 32768
#define Fn 512
#define En 8
#define Hn 128
#define An 256
#define Tn 8
#define HCn 32
#define MT 64
#define NTILES_MAX 520

// ---- smem layout (bytes) ----
#define XS0   0         // 2 x 6144 x tiles ([64][24] bf16 hi + lo); doubles as f32 staging
#define BT0   12288     // weight tile buffers: 2 x 8704 ([16][136] bf16 hi at +0, lo at +4352)
#define HH    29696     // [64][136] bf16 (17408) -- h hi only (2-term GEMM2)
#define RIDX  47104
#define ACTS  47360
#define AB1   47616
#define AB2   48128
#define CB1   49152
#define CW2S  49280
#define SMEM_TOTAL 49408

// ---- device scratch ----
__device__ int g_acnt[En];
__device__ int g_ccnt[Tn];
__device__ int g_alist[En * Bn];
__device__ int g_clist[Tn * Bn];
__device__ __nv_bfloat16 g_aw1h[En * Fn * Hn];
__device__ __nv_bfloat16 g_aw1l[En * Fn * Hn];
__device__ __nv_bfloat16 g_aw2h[En * Hn * An];
__device__ __nv_bfloat16 g_aw2l[En * Hn * An];
__device__ __nv_bfloat16 g_cw1h[Tn * Fn * HCn];
__device__ __nv_bfloat16 g_cw1l[Tn * Fn * HCn];

typedef wmma::fragment<wmma::matrix_a, 16, 16, 16, __nv_bfloat16, wmma::row_major> FragA;
typedef wmma::fragment<wmma::matrix_b, 16, 16, 16, __nv_bfloat16, wmma::row_major> FragB;
typedef wmma::fragment<wmma::accumulator, 16, 16, 16, float> FragC;

// ---------------- routing ----------------
__global__ void zero_kernel() {
    int t = threadIdx.x;
    if (t < En) g_acnt[t] = 0;
    if (t < Tn) g_ccnt[t] = 0;
}

__global__ void route_kernel(const int* __restrict__ commands,
                             const int* __restrict__ tasks) {
    __shared__ int scA[En], scC[Tn], baseA[En], baseC[Tn];
    int tid = threadIdx.x;
    if (tid < En) scA[tid] = 0;
    if (tid < Tn) scC[tid] = 0;
    __syncthreads();
    int b = blockIdx.x * blockDim.x + tid;
    int e = commands[b];
    int pa = atomicAdd(&scA[e], 1);
    int t = tasks[b];
    int pc = atomicAdd(&scC[t], 1);
    __syncthreads();
    if (tid < En) baseA[tid] = atomicAdd(&g_acnt[tid], scA[tid]);
    if (tid < Tn) baseC[tid] = atomicAdd(&g_ccnt[tid], scC[tid]);
    __syncthreads();
    g_alist[e * Bn + baseA[e] + pa] = b;
    g_clist[t * Bn + baseC[t] + pc] = b;
}

// ---------------- weight split prep ----------------
__global__ void prep_kernel(const float* __restrict__ AW1, const float* __restrict__ AW2,
                            const float* __restrict__ CW1) {
    int i = blockIdx.x * 256 + threadIdx.x;
    if (i < En * Fn * Hn) {
        float f = AW1[i];
        __nv_bfloat16 h = __float2bfloat16(f);
        g_aw1h[i] = h;
        g_aw1l[i] = __float2bfloat16(f - __bfloat162float(h));
    } else if (i < En * Fn * Hn + En * Hn * An) {
        int j = i - En * Fn * Hn;
        float f = AW2[j];
        __nv_bfloat16 h = __float2bfloat16(f);
        g_aw2h[j] = h;
        g_aw2l[j] = __float2bfloat16(f - __bfloat162float(h));
    } else if (i < En * Fn * Hn + En * Hn * An + Tn * Fn * HCn) {
        int j = i - En * Fn * Hn - En * Hn * An;
        float f = CW1[j];
        __nv_bfloat16 h = __float2bfloat16(f);
        g_cw1h[j] = h;
        g_cw1l[j] = __float2bfloat16(f - __bfloat162float(h));
    }
}

// ---------------- helpers ----------------
__device__ __forceinline__ uint32_t pk(float a, float b) {
    __nv_bfloat162 t = __floats2bfloat162_rn(a, b);
    return *reinterpret_cast<uint32_t*>(&t);
}

__device__ __forceinline__ void split8(const float* f, uint4& hi, uint4& lo) {
    float fh[8], fl[8];
#pragma unroll
    for (int i = 0; i < 8; i++) {
        float h = __bfloat162float(__float2bfloat16(f[i]));
        fh[i] = h;
        fl[i] = f[i] - h;
    }
    hi = make_uint4(pk(fh[0], fh[1]), pk(fh[2], fh[3]), pk(fh[4], fh[5]), pk(fh[6], fh[7]));
    lo = make_uint4(pk(fl[0], fl[1]), pk(fl[2], fl[3]), pk(fl[4], fl[5]), pk(fl[6], fl[7]));
}

__device__ __forceinline__ uint32_t s2u(const void* p) {
    return (uint32_t)__cvta_generic_to_shared(p);
}
__device__ __forceinline__ void cpa(uint32_t d, const void* s) {
    asm volatile("cp.async.cg.shared.global [%0], [%1], 16;" :: "r"(d), "l"(s));
}
#define CPC() asm volatile("cp.async.commit_group;")
#define CPW1() asm volatile("cp.async.wait_group 1;")
#define CPW0() asm volatile("cp.async.wait_group 0;")

// raw mma helpers (m16n8k16 bf16, documented layouts)
__device__ __forceinline__ void ldsm4(uint32_t* r, uint32_t addr) {
    asm volatile("ldmatrix.sync.aligned.m8n8.x4.shared.b16 {%0,%1,%2,%3}, [%4];"
        : "=r"(r[0]), "=r"(r[1]), "=r"(r[2]), "=r"(r[3]) : "r"(addr));
}
__device__ __forceinline__ void ldsm2t(uint32_t* r, uint32_t addr) {
    asm volatile("ldmatrix.sync.aligned.m8n8.x2.trans.shared.b16 {%0,%1}, [%2];"
        : "=r"(r[0]), "=r"(r[1]) : "r"(addr));
}
__device__ __forceinline__ void mma16816(float* c, const uint32_t* a, const uint32_t* b) {
    asm volatile("mma.sync.aligned.m16n8k16.row.col.f32.bf16.bf16.f32 "
        "{%0,%1,%2,%3}, {%4,%5,%6,%7}, {%8,%9}, {%0,%1,%2,%3};"
        : "+f"(c[0]), "+f"(c[1]), "+f"(c[2]), "+f"(c[3])
        : "r"(a[0]), "r"(a[1]), "r"(a[2]), "r"(a[3]), "r"(b[0]), "r"(b[1]));
}

// load 8 fp32 of this thread's row slice (16-col slice, lane pair splits 8/8)
__device__ __forceinline__ void ldx8(float* r, const float* __restrict__ x, int grow,
                                     int kc, int tid) {
    const float4* s = (const float4*)(x + (size_t)grow * Fn + kc * 16 + (tid & 1) * 8);
    float4 v;
    v = s[0]; r[0] = v.x; r[1] = v.y; r[2] = v.z; r[3] = v.w;
    v = s[1]; r[4] = v.x; r[5] = v.y; r[6] = v.z; r[7] = v.w;
}

// split regs, store into XS buffer b ([64][24] bf16, hi at +0, lo at +3072)
__device__ __forceinline__ void stx8(unsigned char* sm, int b, const float* r, int tid) {
    uint4 hi, lo;
    split8(r, hi, lo);
    uint32_t a = (uint32_t)((tid >> 1) * 48 + (tid & 1) * 16);
    *(uint4*)(sm + XS0 + b * 6144 + a) = hi;
    *(uint4*)(sm + XS0 + b * 6144 + 3072 + a) = lo;
}

// hi-only variant (actor GEMM1: x rounded to bf16, no lo term)
__device__ __forceinline__ void stx8h(unsigned char* sm, int b, const float* r, int tid) {
    uint4 hi = make_uint4(pk(r[0], r[1]), pk(r[2], r[3]), pk(r[4], r[5]), pk(r[6], r[7]));
    uint32_t a = (uint32_t)((tid >> 1) * 48 + (tid & 1) * 16);
    *(uint4*)(sm + XS0 + b * 6144 + a) = hi;
}

// W1 slice kc16 (16 k-rows x 128 cols) -> BT buffer (hi +0, lo +4352, stride 272B)
__device__ __forceinline__ void issue_w1(unsigned char* sm, int b, int grp, int kc16, int tid) {
    int k = tid >> 3, seg = tid & 7;
    size_t gb = (((size_t)grp * Fn + kc16 * 16 + k) << 7) + seg * 16;
    uint32_t d = s2u(sm + BT0) + b * 8704 + k * 272 + seg * 32;
    cpa(d, g_aw1h + gb);
    cpa(d + 16, g_aw1h + gb + 8);
    cpa(d + 4352, g_aw1l + gb);
    cpa(d + 4352 + 16, g_aw1l + gb + 8);
}
// W2 slice kcg (0..15): N-half = kcg>>3, local k-slice = kcg&7
__device__ __forceinline__ void issue_w2(unsigned char* sm, int b, int grp, int kcg, int tid) {
    int k = tid >> 3, seg = tid & 7;
    size_t gb = ((size_t)grp * Hn + (kcg & 7) * 16 + k) * An + (kcg >> 3) * 128 + seg * 16;
    uint32_t d = s2u(sm + BT0) + b * 8704 + k * 272 + seg * 32;
    cpa(d, g_aw2h + gb);
    cpa(d + 16, g_aw2h + gb + 8);
    cpa(d + 4352, g_aw2l + gb);
    cpa(d + 4352 + 16, g_aw2l + gb + 8);
}
// critic W1 slice (16 x 32), buffer b at BT0 + b*2560 (hi stride 80B, lo +1280)
__device__ __forceinline__ void issue_cw(unsigned char* sm, int b, int grp, int kc16, int tid) {
    if (tid < 64) {
        int row = tid >> 2, seg = tid & 3;
        size_t gb = ((size_t)grp * Fn + kc16 * 16 + row) * HCn + seg * 8;
        uint32_t d = s2u(sm + BT0) + b * 2560 + row * 80 + seg * 16;
        cpa(d, g_cw1h + gb);
        cpa(d + 1280, g_cw1l + gb);
    }
}

// ---------------- fused actor + critic ----------------
extern "C" __global__ void __launch_bounds__(128, 4)
fused_kernel(const float* __restrict__ x, const int* __restrict__ actions,
             const float* __restrict__ Ab1, const float* __restrict__ Ab2,
             const float* __restrict__ Cb1, const float* __restrict__ CW2,
             const float* __restrict__ Cb2, float* __restrict__ out) {
    extern __shared__ unsigned char sm[];
    int tid = threadIdx.x;
    int wid = tid >> 5;
    int wm = wid >> 1;
    int wn = wid & 1;
    int lane = tid & 31;
    bool is_actor = (blockIdx.z == 0);

    int grp = -1, local = blockIdx.x;
    const int* cnts = is_actor ? g_acnt : g_ccnt;
#pragma unroll
    for (int i = 0; i < En; i++) {
        int nt = (cnts[i] + MT - 1) / MT;
        if (grp < 0) {
            if (local < nt) grp = i;
            else local -= nt;
        }
    }
    if (grp < 0) return;
    int cnt = cnts[grp];
    int r0 = local * MT;

    int* ridx = (int*)(sm + RIDX);
    int* acts = (int*)(sm + ACTS);
    if (tid < MT) {
        int r = r0 + tid;
        const int* list = is_actor ? (g_alist + grp * Bn) : (g_clist + grp * Bn);
        int idx = (r < cnt) ? list[r] : -1;
        ridx[tid] = idx;
        if (is_actor) acts[tid] = (idx >= 0) ? actions[idx] : 0;
    }
    if (is_actor) {
        ((float*)(sm + AB1))[tid] = Ab1[grp * Hn + tid];
        ((float*)(sm + AB2))[tid] = Ab2[grp * An + tid];
        ((float*)(sm + AB2))[128 + tid] = Ab2[grp * An + 128 + tid];
    } else if (tid < HCn) {
        ((float*)(sm + CB1))[tid] = Cb1[grp * HCn + tid];
        ((float*)(sm + CW2S))[tid] = CW2[grp * HCn + tid];
    }
    __syncthreads();
    int rr = ridx[tid >> 1];
    int grow = rr < 0 ? 0 : rr;
    float xr[8];
    float* stg = (float*)(sm + XS0);  // f32 staging over dead XS region (critic + merge)

    if (is_actor) {
        uint32_t hhb = s2u(sm + HH);
        uint32_t btb = s2u(sm + BT0);
        uint32_t xsb = s2u(sm + XS0);
        // accumulators: [mi][j][4], rows wm*32+mi*16+(lane>>2)+(k>>1)*8,
        // cols wn*64+j*8+2*(lane&3)+(k&1)
        float accr[2][8][4];
#pragma unroll
        for (int mi = 0; mi < 2; mi++)
#pragma unroll
            for (int j = 0; j < 8; j++)
#pragma unroll
                for (int k = 0; k < 4; k++) accr[mi][j][k] = 0.f;

        // ======== GEMM1: h ≈ x_hi @ (W1h+W1l) [64 x 512 x 128], 2-term ========
        ldx8(xr, x, grow, 0, tid);
        stx8h(sm, 0, xr, tid);
        ldx8(xr, x, grow, 1, tid);
        issue_w1(sm, 0, grp, 0, tid);
        CPC();

        for (int kc = 0; kc < 32; kc++) {
            int b = kc & 1;
            __syncthreads();  // (A)
            if (kc < 31) issue_w1(sm, b ^ 1, grp, kc + 1, tid);
            else issue_w2(sm, 0, grp, 0, tid);  // prefetch GEMM2 kcg0 -> buf0
            CPC();
            CPW1();
            __syncthreads();  // (B)
            uint32_t xs = xsb + b * 6144;
            uint32_t bt = btb + b * 8704;
            uint32_t ah[2][4];
#pragma unroll
            for (int mi = 0; mi < 2; mi++) {
                uint32_t aaddr = xs +
                    ((wm * 32 + mi * 16 + (lane & 15)) * 24 + (lane >> 4) * 8) * 2;
                ldsm4(ah[mi], aaddr);
            }
#pragma unroll
            for (int j = 0; j < 8; j++) {
                uint32_t bhf[2], blf[2];
                uint32_t baddr = bt + ((lane & 15) * 136 + wn * 64 + j * 8) * 2;
                ldsm2t(bhf, baddr);
                ldsm2t(blf, baddr + 4352);
#pragma unroll
                for (int mi = 0; mi < 2; mi++) {
                    mma16816(accr[mi][j], ah[mi], bhf);
                    mma16816(accr[mi][j], ah[mi], blf);
                }
            }
            if (kc < 31) {
                stx8h(sm, b ^ 1, xr, tid);
                if (kc < 30) ldx8(xr, x, grow, kc + 2, tid);
            }
        }

        // ---- GEMM1 epilogue: register bias+relu+bf16, direct STS to HH ----
        // (ordered before GEMM2's ldsm by GEMM2's (A)+(B) barriers)
        {
            int c0 = wn * 64 + 2 * (lane & 3);
            int rbase = wm * 32 + (lane >> 2);
#pragma unroll
            for (int mi = 0; mi < 2; mi++)
#pragma unroll
                for (int j = 0; j < 8; j++) {
                    float2 bb = *(const float2*)((const float*)(sm + AB1) + c0 + j * 8);
                    float v0 = accr[mi][j][0] + bb.x, v1 = accr[mi][j][1] + bb.y;
                    float v2 = accr[mi][j][2] + bb.x, v3 = accr[mi][j][3] + bb.y;
                    v0 = v0 > 0.f ? v0 : 0.f; v1 = v1 > 0.f ? v1 : 0.f;
                    v2 = v2 > 0.f ? v2 : 0.f; v3 = v3 > 0.f ? v3 : 0.f;
                    int row0 = rbase + mi * 16;
                    *(uint32_t*)(sm + HH + (row0 * 136 + c0 + j * 8) * 2) = pk(v0, v1);
                    *(uint32_t*)(sm + HH + ((row0 + 8) * 136 + c0 + j * 8) * 2) = pk(v2, v3);
                }
        }

        // ======== GEMM2: raw mma, register softmax (2-term) ========
        int rws[4], mact[4];
#pragma unroll
        for (int s = 0; s < 4; s++) {
            rws[s] = wm * 32 + (s >> 1) * 16 + (lane >> 2) + (s & 1) * 8;
            mact[s] = acts[rws[s]];
        }
        float mrun[4], zrun[4], s1run[4], schrun[4];
#pragma unroll
        for (int s = 0; s < 4; s++) {
            mrun[s] = -3e38f; zrun[s] = 0.f; s1run[s] = 0.f; schrun[s] = -3e38f;
        }

#pragma unroll 1
        for (int half = 0; half < 2; half++) {
#pragma unroll
            for (int mi = 0; mi < 2; mi++)
#pragma unroll
                for (int j = 0; j < 8; j++)
#pragma unroll
                    for (int k = 0; k < 4; k++) accr[mi][j][k] = 0.f;
#pragma unroll 1
            for (int kcl = 0; kcl < 8; kcl++) {
                int kcg = half * 8 + kcl;
                int b = kcg & 1;
                __syncthreads();  // (A)
                if (kcg < 15) {
                    issue_w2(sm, b ^ 1, grp, kcg + 1, tid);
                    CPC();
                    CPW1();
                } else {
                    CPW0();
                }
                __syncthreads();  // (B)
                uint32_t bt = btb + b * 8704;
                uint32_t af[2][4];
#pragma unroll
                for (int mi = 0; mi < 2; mi++) {
                    uint32_t aaddr = hhb +
                        ((wm * 32 + mi * 16 + (lane & 15)) * 136 + kcl * 16 +
                         (lane >> 4) * 8) * 2;
                    ldsm4(af[mi], aaddr);
                }
#pragma unroll
                for (int j = 0; j < 8; j++) {
                    uint32_t bhf[2], blf[2];
                    uint32_t baddr = bt + ((lane & 15) * 136 + wn * 64 + j * 8) * 2;
                    ldsm2t(bhf, baddr);
                    ldsm2t(blf, baddr + 4352);
#pragma unroll
                    for (int mi = 0; mi < 2; mi++) {
                        mma16816(accr[mi][j], af[mi], bhf);
                        mma16816(accr[mi][j], af[mi], blf);
                    }
                }
            }
            // ---- register epilogue: bias + per-warp online softmax partials ----
            int cb = half * 128 + wn * 64 + 2 * (lane & 3);
            float mx[4] = {-3e38f, -3e38f, -3e38f, -3e38f};
#pragma unroll
            for (int mi = 0; mi < 2; mi++)
#pragma unroll
                for (int j = 0; j < 8; j++) {
                    float2 bb = *(const float2*)((const float*)(sm + AB2) + cb + j * 8);
                    accr[mi][j][0] += bb.x; accr[mi][j][1] += bb.y;
                    accr[mi][j][2] += bb.x; accr[mi][j][3] += bb.y;
                    mx[mi * 2] = fmaxf(mx[mi * 2], fmaxf(accr[mi][j][0], accr[mi][j][1]));
                    mx[mi * 2 + 1] = fmaxf(mx[mi * 2 + 1], fmaxf(accr[mi][j][2], accr[mi][j][3]));
                }
#pragma unroll
            for (int s = 0; s < 4; s++) {
                mx[s] = fmaxf(mx[s], __shfl_xor_sync(0xffffffffu, mx[s], 1));
                mx[s] = fmaxf(mx[s], __shfl_xor_sync(0xffffffffu, mx[s], 2));
            }
            float zz[4] = {0.f, 0.f, 0.f, 0.f}, ss[4] = {0.f, 0.f, 0.f, 0.f};
            float sc[4] = {-3e38f, -3e38f, -3e38f, -3e38f};
#pragma unroll
            for (int mi = 0; mi < 2; mi++)
#pragma unroll
                for (int j = 0; j < 8; j++) {
                    int c0 = cb + j * 8;
                    int s0 = mi * 2, s1i = mi * 2 + 1;
                    float v0 = accr[mi][j][0], v1 = accr[mi][j][1];
                    float v2 = accr[mi][j][2], v3 = accr[mi][j][3];
                    float p0 = __expf(v0 - mx[s0]), p1 = __expf(v1 - mx[s0]);
                    float p2 = __expf(v2 - mx[s1i]), p3 = __expf(v3 - mx[s1i]);
                    zz[s0] += p0 + p1;  ss[s0] += v0 * p0 + v1 * p1;
                    zz[s1i] += p2 + p3; ss[s1i] += v2 * p2 + v3 * p3;
                    if (c0 == mact[s0]) sc[s0] = v0;
                    if (c0 + 1 == mact[s0]) sc[s0] = v1;
                    if (c0 == mact[s1i]) sc[s1i] = v2;
                    if (c0 + 1 == mact[s1i]) sc[s1i] = v3;
                }
#pragma unroll
            for (int s = 0; s < 4; s++) {
                zz[s] += __shfl_xor_sync(0xffffffffu, zz[s], 1);
                zz[s] += __shfl_xor_sync(0xffffffffu, zz[s], 2);
                ss[s] += __shfl_xor_sync(0xffffffffu, ss[s], 1);
                ss[s] += __shfl_xor_sync(0xffffffffu, ss[s], 2);
                sc[s] = fmaxf(sc[s], __shfl_xor_sync(0xffffffffu, sc[s], 1));
                sc[s] = fmaxf(sc[s], __shfl_xor_sync(0xffffffffu, sc[s], 2));
                float M = fmaxf(mrun[s], mx[s]);
                float e1 = __expf(mrun[s] - M), e2 = __expf(mx[s] - M);
                zrun[s] = zrun[s] * e1 + zz[s] * e2;
                s1run[s] = s1run[s] * e1 + ss[s] * e2;
                mrun[s] = M;
                schrun[s] = fmaxf(schrun[s], sc[s]);
            }
        }
        // ---- cross-warp (wn) merge via stg; wn==0 writes output ----
        __syncthreads();
        if (wn == 1 && (lane & 3) == 0) {
#pragma unroll
            for (int s = 0; s < 4; s++)
                *(float4*)(stg + rws[s] * 4) =
                    make_float4(mrun[s], zrun[s], s1run[s], schrun[s]);
        }
        __syncthreads();
        if (wn == 0 && (lane & 3) == 0) {
#pragma unroll
            for (int s = 0; s < 4; s++) {
                float4 o = *(const float4*)(stg + rws[s] * 4);
                float M = fmaxf(mrun[s], o.x);
                float e1 = __expf(mrun[s] - M), e2 = __expf(o.x - M);
                float z = zrun[s] * e1 + o.y * e2;
                float s1 = s1run[s] * e1 + o.z * e2;
                float sch = fmaxf(schrun[s], o.w);
                int rt = rws[s];
                if (r0 + rt < cnt) {
                    int b = ridx[rt];
                    float lz = M + __logf(z);
                    out[(size_t)b * 3 + 0] = sch - lz;
                    out[(size_t)b * 3 + 2] = s1 / z - lz;
                }
            }
        }
    } else {
        // ======== Critic [64 x 512 x 32], K-slice 16, 3-term, pipelined ========
        FragC acc[2];
        wmma::fill_fragment(acc[0], 0.f);
        wmma::fill_fragment(acc[1], 0.f);

        ldx8(xr, x, grow, 0, tid);
        stx8(sm, 0, xr, tid);
        ldx8(xr, x, grow, 1, tid);
        issue_cw(sm, 0, grp, 0, tid);
        CPC();

        for (int kc = 0; kc < 32; kc++) {
            int b = kc & 1;
            __syncthreads();  // (A)
            if (kc < 31) {
                issue_cw(sm, b ^ 1, grp, kc + 1, tid);
                CPC();
                CPW1();
            } else {
                CPW0();
            }
            __syncthreads();  // (B)
            const __nv_bfloat16* xh = (const __nv_bfloat16*)(sm + XS0 + b * 6144);
            const __nv_bfloat16* bh = (const __nv_bfloat16*)(sm + BT0 + b * 2560);
            FragA ah[2], al[2];
#pragma unroll
            for (int mi = 0; mi < 2; mi++) {
                wmma::load_matrix_sync(ah[mi], xh + (wm * 32 + mi * 16) * 24, 24);
                wmma::load_matrix_sync(al[mi], xh + 1536 + (wm * 32 + mi * 16) * 24, 24);
            }
            FragB fbh, fbl;
            wmma::load_matrix_sync(fbh, bh + wn * 16, 40);
            wmma::load_matrix_sync(fbl, bh + 640 + wn * 16, 40);
#pragma unroll
            for (int mi = 0; mi < 2; mi++) {
                wmma::mma_sync(acc[mi], ah[mi], fbh, acc[mi]);
                wmma::mma_sync(acc[mi], ah[mi], fbl, acc[mi]);
                wmma::mma_sync(acc[mi], al[mi], fbh, acc[mi]);
            }
            if (kc < 31) {
                stx8(sm, b ^ 1, xr, tid);
                if (kc < 30) ldx8(xr, x, grow, kc + 2, tid);
            }
        }
        __syncthreads();
#pragma unroll
        for (int mi = 0; mi < 2; mi++)
            wmma::store_matrix_sync(stg + (wm * 32 + mi * 16) * 36 + wn * 16, acc[mi], 36,
                                    wmma::mem_row_major);
        __syncthreads();
        {
            int row = tid >> 1, c0 = (tid & 1) * 16;
            const float4* hp = (const float4*)(stg + row * 36 + c0);
            const float4* b1p = (const float4*)((float*)(sm + CB1) + c0);
            const float4* w2p = (const float4*)((float*)(sm + CW2S) + c0);
            float sum = 0.f;
#pragma unroll
            for (int g = 0; g < 4; g++) {
                float4 h4 = hp[g], b4 = b1p[g], w4 = w2p[g];
                float h;
                h = h4.x + b4.x; sum += (h > 0.f ? h : 0.f) * w4.x;
                h = h4.y + b4.y; sum += (h > 0.f ? h : 0.f) * w4.y;
                h = h4.z + b4.z; sum += (h > 0.f ? h : 0.f) * w4.z;
                h = h4.w + b4.w; sum += (h > 0.f ? h : 0.f) * w4.w;
            }
            sum += __shfl_xor_sync(0xffffffffu, sum, 1);
            if ((tid & 1) == 0 && r0 + row < cnt)
                out[(size_t)ridx[row] * 3 + 1] = sum + Cb2[grp];
        }
    }
}

extern "C" void kernel_launch(void* const* d_in, const int* in_sizes, int n_in,
                              void* d_out, int out_size) {
    const float* x = (const float*)d_in[0];
    const int* commands = (const int*)d_in[1];
    const int* tasks = (const int*)d_in[2];
    const int* actions = (const int*)d_in[3];
    const float* A_W1 = (const float*)d_in[4];
    const float* A_b1 = (const float*)d_in[5];
    const float* A_W2 = (const float*)d_in[6];
    const float* A_b2 = (const float*)d_in[7];
    const float* C_W1 = (const float*)d_in[8];
    const float* C_b1 = (const float*)d_in[9];
    const float* C_W2 = (const float*)d_in[10];
    const float* C_b2 = (const float*)d_in[11];
    float* out = (float*)d_out;

    cudaFuncSetAttribute(fused_kernel, cudaFuncAttributeMaxDynamicSharedMemorySize,
                         SMEM_TOTAL);

    zero_kernel<<<1, 32>>>();
    route_kernel<<<Bn / 256, 256>>>(commands, tasks);
    int prep_elems = En * Fn * Hn + En * Hn * An + Tn * Fn * HCn;
    prep_kernel<<<(prep_elems + 255) / 256, 256>>>(A_W1, A_W2, C_W1);
    fused_kernel<<<dim3(NTILES_MAX, 1, 2), 128, SMEM_TOTAL>>>(
        x, actions, A_b1, A_b2, C_b1, C_W2, C_b2, out);
}

// round 17
// speedup vs baseline: 1.7553x; 1.1958x over previous
#include <cuda_runtime.h>
#include <cuda_bf16.h>
#include <mma.h>
#include <cstdint>

using namespace nvcuda;

#define Bn 32768
#define Fn 512
#define En 8
#define Hn 128
#define An 256
#define Tn 8
#define HCn 32
#define MT 64
#define NTILES_MAX 520

// ---- smem layout (bytes) ----
#define XS0   0         // 2 x 6144 x tiles ([64][24] bf16 hi + lo); doubles as f32 staging
#define BT0   12288     // weight tile buffers: 2 x 4352 ([16][136] bf16, hi only)
#define HH    20992     // [64][136] bf16 (17408) -- h hi only
#define RIDX  38400
#define ACTS  38656
#define AB1   38912
#define AB2   39424
#define CB1   40448
#define CW2S  40576
#define SMEM_TOTAL 40704

// ---- device scratch ----
__device__ int g_acnt[En];
__device__ int g_ccnt[Tn];
__device__ int g_alist[En * Bn];
__device__ int g_clist[Tn * Bn];
__device__ __nv_bfloat16 g_aw1h[En * Fn * Hn];
__device__ __nv_bfloat16 g_aw2h[En * Hn * An];
__device__ __nv_bfloat16 g_cw1h[Tn * Fn * HCn];
__device__ __nv_bfloat16 g_cw1l[Tn * Fn * HCn];

typedef wmma::fragment<wmma::matrix_a, 16, 16, 16, __nv_bfloat16, wmma::row_major> FragA;
typedef wmma::fragment<wmma::matrix_b, 16, 16, 16, __nv_bfloat16, wmma::row_major> FragB;
typedef wmma::fragment<wmma::accumulator, 16, 16, 16, float> FragC;

// ---------------- routing ----------------
__global__ void zero_kernel() {
    int t = threadIdx.x;
    if (t < En) g_acnt[t] = 0;
    if (t < Tn) g_ccnt[t] = 0;
}

__global__ void route_kernel(const int* __restrict__ commands,
                             const int* __restrict__ tasks) {
    __shared__ int scA[En], scC[Tn], baseA[En], baseC[Tn];
    int tid = threadIdx.x;
    if (tid < En) scA[tid] = 0;
    if (tid < Tn) scC[tid] = 0;
    __syncthreads();
    int b = blockIdx.x * blockDim.x + tid;
    int e = commands[b];
    int pa = atomicAdd(&scA[e], 1);
    int t = tasks[b];
    int pc = atomicAdd(&scC[t], 1);
    __syncthreads();
    if (tid < En) baseA[tid] = atomicAdd(&g_acnt[tid], scA[tid]);
    if (tid < Tn) baseC[tid] = atomicAdd(&g_ccnt[tid], scC[tid]);
    __syncthreads();
    g_alist[e * Bn + baseA[e] + pa] = b;
    g_clist[t * Bn + baseC[t] + pc] = b;
}

// ---------------- weight prep: actor hi-only, critic split ----------------
__global__ void prep_kernel(const float* __restrict__ AW1, const float* __restrict__ AW2,
                            const float* __restrict__ CW1) {
    int i = blockIdx.x * 256 + threadIdx.x;
    if (i < En * Fn * Hn) {
        g_aw1h[i] = __float2bfloat16(AW1[i]);
    } else if (i < En * Fn * Hn + En * Hn * An) {
        int j = i - En * Fn * Hn;
        g_aw2h[j] = __float2bfloat16(AW2[j]);
    } else if (i < En * Fn * Hn + En * Hn * An + Tn * Fn * HCn) {
        int j = i - En * Fn * Hn - En * Hn * An;
        float f = CW1[j];
        __nv_bfloat16 h = __float2bfloat16(f);
        g_cw1h[j] = h;
        g_cw1l[j] = __float2bfloat16(f - __bfloat162float(h));
    }
}

// ---------------- helpers ----------------
__device__ __forceinline__ uint32_t pk(float a, float b) {
    __nv_bfloat162 t = __floats2bfloat162_rn(a, b);
    return *reinterpret_cast<uint32_t*>(&t);
}

__device__ __forceinline__ void split8(const float* f, uint4& hi, uint4& lo) {
    float fh[8], fl[8];
#pragma unroll
    for (int i = 0; i < 8; i++) {
        float h = __bfloat162float(__float2bfloat16(f[i]));
        fh[i] = h;
        fl[i] = f[i] - h;
    }
    hi = make_uint4(pk(fh[0], fh[1]), pk(fh[2], fh[3]), pk(fh[4], fh[5]), pk(fh[6], fh[7]));
    lo = make_uint4(pk(fl[0], fl[1]), pk(fl[2], fl[3]), pk(fl[4], fl[5]), pk(fl[6], fl[7]));
}

__device__ __forceinline__ uint32_t s2u(const void* p) {
    return (uint32_t)__cvta_generic_to_shared(p);
}
__device__ __forceinline__ void cpa(uint32_t d, const void* s) {
    asm volatile("cp.async.cg.shared.global [%0], [%1], 16;" :: "r"(d), "l"(s));
}
#define CPC() asm volatile("cp.async.commit_group;")
#define CPW1() asm volatile("cp.async.wait_group 1;")
#define CPW0() asm volatile("cp.async.wait_group 0;")

// raw mma helpers (m16n8k16 bf16, documented layouts)
__device__ __forceinline__ void ldsm4(uint32_t* r, uint32_t addr) {
    asm volatile("ldmatrix.sync.aligned.m8n8.x4.shared.b16 {%0,%1,%2,%3}, [%4];"
        : "=r"(r[0]), "=r"(r[1]), "=r"(r[2]), "=r"(r[3]) : "r"(addr));
}
__device__ __forceinline__ void ldsm2t(uint32_t* r, uint32_t addr) {
    asm volatile("ldmatrix.sync.aligned.m8n8.x2.trans.shared.b16 {%0,%1}, [%2];"
        : "=r"(r[0]), "=r"(r[1]) : "r"(addr));
}
__device__ __forceinline__ void mma16816(float* c, const uint32_t* a, const uint32_t* b) {
    asm volatile("mma.sync.aligned.m16n8k16.row.col.f32.bf16.bf16.f32 "
        "{%0,%1,%2,%3}, {%4,%5,%6,%7}, {%8,%9}, {%0,%1,%2,%3};"
        : "+f"(c[0]), "+f"(c[1]), "+f"(c[2]), "+f"(c[3])
        : "r"(a[0]), "r"(a[1]), "r"(a[2]), "r"(a[3]), "r"(b[0]), "r"(b[1]));
}

// load 8 fp32 of this thread's row slice (16-col slice, lane pair splits 8/8)
__device__ __forceinline__ void ldx8(float* r, const float* __restrict__ x, int grow,
                                     int kc, int tid) {
    const float4* s = (const float4*)(x + (size_t)grow * Fn + kc * 16 + (tid & 1) * 8);
    float4 v;
    v = s[0]; r[0] = v.x; r[1] = v.y; r[2] = v.z; r[3] = v.w;
    v = s[1]; r[4] = v.x; r[5] = v.y; r[6] = v.z; r[7] = v.w;
}

// split regs, store into XS buffer b ([64][24] bf16, hi at +0, lo at +3072)
__device__ __forceinline__ void stx8(unsigned char* sm, int b, const float* r, int tid) {
    uint4 hi, lo;
    split8(r, hi, lo);
    uint32_t a = (uint32_t)((tid >> 1) * 48 + (tid & 1) * 16);
    *(uint4*)(sm + XS0 + b * 6144 + a) = hi;
    *(uint4*)(sm + XS0 + b * 6144 + 3072 + a) = lo;
}

// hi-only variant (actor GEMM1: x rounded to bf16, no lo term)
__device__ __forceinline__ void stx8h(unsigned char* sm, int b, const float* r, int tid) {
    uint4 hi = make_uint4(pk(r[0], r[1]), pk(r[2], r[3]), pk(r[4], r[5]), pk(r[6], r[7]));
    uint32_t a = (uint32_t)((tid >> 1) * 48 + (tid & 1) * 16);
    *(uint4*)(sm + XS0 + b * 6144 + a) = hi;
}

// W1 slice kc16 (16 k-rows x 128 cols, hi only) -> BT buffer (stride 272B)
__device__ __forceinline__ void issue_w1(unsigned char* sm, int b, int grp, int kc16, int tid) {
    int k = tid >> 3, seg = tid & 7;
    size_t gb = (((size_t)grp * Fn + kc16 * 16 + k) << 7) + seg * 16;
    uint32_t d = s2u(sm + BT0) + b * 4352 + k * 272 + seg * 32;
    cpa(d, g_aw1h + gb);
    cpa(d + 16, g_aw1h + gb + 8);
}
// W2 slice kcg (0..15): N-half = kcg>>3, local k-slice = kcg&7 (hi only)
__device__ __forceinline__ void issue_w2(unsigned char* sm, int b, int grp, int kcg, int tid) {
    int k = tid >> 3, seg = tid & 7;
    size_t gb = ((size_t)grp * Hn + (kcg & 7) * 16 + k) * An + (kcg >> 3) * 128 + seg * 16;
    uint32_t d = s2u(sm + BT0) + b * 4352 + k * 272 + seg * 32;
    cpa(d, g_aw2h + gb);
    cpa(d + 16, g_aw2h + gb + 8);
}
// critic W1 slice (16 x 32), buffer b at BT0 + b*2560 (hi stride 80B, lo +1280)
__device__ __forceinline__ void issue_cw(unsigned char* sm, int b, int grp, int kc16, int tid) {
    if (tid < 64) {
        int row = tid >> 2, seg = tid & 3;
        size_t gb = ((size_t)grp * Fn + kc16 * 16 + row) * HCn + seg * 8;
        uint32_t d = s2u(sm + BT0) + b * 2560 + row * 80 + seg * 16;
        cpa(d, g_cw1h + gb);
        cpa(d + 1280, g_cw1l + gb);
    }
}

// ---------------- fused actor + critic ----------------
extern "C" __global__ void __launch_bounds__(128, 4)
fused_kernel(const float* __restrict__ x, const int* __restrict__ actions,
             const float* __restrict__ Ab1, const float* __restrict__ Ab2,
             const float* __restrict__ Cb1, const float* __restrict__ CW2,
             const float* __restrict__ Cb2, float* __restrict__ out) {
    extern __shared__ unsigned char sm[];
    int tid = threadIdx.x;
    int wid = tid >> 5;
    int wm = wid >> 1;
    int wn = wid & 1;
    int lane = tid & 31;
    bool is_actor = (blockIdx.z == 0);

    int grp = -1, local = blockIdx.x;
    const int* cnts = is_actor ? g_acnt : g_ccnt;
#pragma unroll
    for (int i = 0; i < En; i++) {
        int nt = (cnts[i] + MT - 1) / MT;
        if (grp < 0) {
            if (local < nt) grp = i;
            else local -= nt;
        }
    }
    if (grp < 0) return;
    int cnt = cnts[grp];
    int r0 = local * MT;

    int* ridx = (int*)(sm + RIDX);
    int* acts = (int*)(sm + ACTS);
    if (tid < MT) {
        int r = r0 + tid;
        const int* list = is_actor ? (g_alist + grp * Bn) : (g_clist + grp * Bn);
        int idx = (r < cnt) ? list[r] : -1;
        ridx[tid] = idx;
        if (is_actor) acts[tid] = (idx >= 0) ? actions[idx] : 0;
    }
    if (is_actor) {
        ((float*)(sm + AB1))[tid] = Ab1[grp * Hn + tid];
        ((float*)(sm + AB2))[tid] = Ab2[grp * An + tid];
        ((float*)(sm + AB2))[128 + tid] = Ab2[grp * An + 128 + tid];
    } else if (tid < HCn) {
        ((float*)(sm + CB1))[tid] = Cb1[grp * HCn + tid];
        ((float*)(sm + CW2S))[tid] = CW2[grp * HCn + tid];
    }
    __syncthreads();
    int rr = ridx[tid >> 1];
    int grow = rr < 0 ? 0 : rr;
    float xr[8];
    float* stg = (float*)(sm + XS0);  // f32 staging over dead XS region (critic + merge)

    if (is_actor) {
        uint32_t hhb = s2u(sm + HH);
        uint32_t btb = s2u(sm + BT0);
        uint32_t xsb = s2u(sm + XS0);
        // accumulators: [mi][j][4], rows wm*32+mi*16+(lane>>2)+(k>>1)*8,
        // cols wn*64+j*8+2*(lane&3)+(k&1)
        float accr[2][8][4];
#pragma unroll
        for (int mi = 0; mi < 2; mi++)
#pragma unroll
            for (int j = 0; j < 8; j++)
#pragma unroll
                for (int k = 0; k < 4; k++) accr[mi][j][k] = 0.f;

        // ======== GEMM1: h ≈ x_hi @ W1h [64 x 512 x 128], 1-term ========
        ldx8(xr, x, grow, 0, tid);
        stx8h(sm, 0, xr, tid);
        ldx8(xr, x, grow, 1, tid);
        issue_w1(sm, 0, grp, 0, tid);
        CPC();

        for (int kc = 0; kc < 32; kc++) {
            int b = kc & 1;
            __syncthreads();  // (A)
            if (kc < 31) issue_w1(sm, b ^ 1, grp, kc + 1, tid);
            else issue_w2(sm, 0, grp, 0, tid);  // prefetch GEMM2 kcg0 -> buf0
            CPC();
            CPW1();
            __syncthreads();  // (B)
            uint32_t xs = xsb + b * 6144;
            uint32_t bt = btb + b * 4352;
            uint32_t ah[2][4];
#pragma unroll
            for (int mi = 0; mi < 2; mi++) {
                uint32_t aaddr = xs +
                    ((wm * 32 + mi * 16 + (lane & 15)) * 24 + (lane >> 4) * 8) * 2;
                ldsm4(ah[mi], aaddr);
            }
#pragma unroll
            for (int j = 0; j < 8; j++) {
                uint32_t bhf[2];
                uint32_t baddr = bt + ((lane & 15) * 136 + wn * 64 + j * 8) * 2;
                ldsm2t(bhf, baddr);
#pragma unroll
                for (int mi = 0; mi < 2; mi++) {
                    mma16816(accr[mi][j], ah[mi], bhf);
                }
            }
            if (kc < 31) {
                stx8h(sm, b ^ 1, xr, tid);
                if (kc < 30) ldx8(xr, x, grow, kc + 2, tid);
            }
        }

        // ---- GEMM1 epilogue: register bias+relu+bf16, direct STS to HH ----
        // (ordered before GEMM2's ldsm by GEMM2's (A)+(B) barriers)
        {
            int c0 = wn * 64 + 2 * (lane & 3);
            int rbase = wm * 32 + (lane >> 2);
#pragma unroll
            for (int mi = 0; mi < 2; mi++)
#pragma unroll
                for (int j = 0; j < 8; j++) {
                    float2 bb = *(const float2*)((const float*)(sm + AB1) + c0 + j * 8);
                    float v0 = accr[mi][j][0] + bb.x, v1 = accr[mi][j][1] + bb.y;
                    float v2 = accr[mi][j][2] + bb.x, v3 = accr[mi][j][3] + bb.y;
                    v0 = v0 > 0.f ? v0 : 0.f; v1 = v1 > 0.f ? v1 : 0.f;
                    v2 = v2 > 0.f ? v2 : 0.f; v3 = v3 > 0.f ? v3 : 0.f;
                    int row0 = rbase + mi * 16;
                    *(uint32_t*)(sm + HH + (row0 * 136 + c0 + j * 8) * 2) = pk(v0, v1);
                    *(uint32_t*)(sm + HH + ((row0 + 8) * 136 + c0 + j * 8) * 2) = pk(v2, v3);
                }
        }

        // ======== GEMM2: raw mma, register softmax (1-term) ========
        int rws[4], mact[4];
#pragma unroll
        for (int s = 0; s < 4; s++) {
            rws[s] = wm * 32 + (s >> 1) * 16 + (lane >> 2) + (s & 1) * 8;
            mact[s] = acts[rws[s]];
        }
        float mrun[4], zrun[4], s1run[4], schrun[4];
#pragma unroll
        for (int s = 0; s < 4; s++) {
            mrun[s] = -3e38f; zrun[s] = 0.f; s1run[s] = 0.f; schrun[s] = -3e38f;
        }

#pragma unroll 1
        for (int half = 0; half < 2; half++) {
#pragma unroll
            for (int mi = 0; mi < 2; mi++)
#pragma unroll
                for (int j = 0; j < 8; j++)
#pragma unroll
                    for (int k = 0; k < 4; k++) accr[mi][j][k] = 0.f;
#pragma unroll 1
            for (int kcl = 0; kcl < 8; kcl++) {
                int kcg = half * 8 + kcl;
                int b = kcg & 1;
                __syncthreads();  // (A)
                if (kcg < 15) {
                    issue_w2(sm, b ^ 1, grp, kcg + 1, tid);
                    CPC();
                    CPW1();
                } else {
                    CPW0();
                }
                __syncthreads();  // (B)
                uint32_t bt = btb + b * 4352;
                uint32_t af[2][4];
#pragma unroll
                for (int mi = 0; mi < 2; mi++) {
                    uint32_t aaddr = hhb +
                        ((wm * 32 + mi * 16 + (lane & 15)) * 136 + kcl * 16 +
                         (lane >> 4) * 8) * 2;
                    ldsm4(af[mi], aaddr);
                }
#pragma unroll
                for (int j = 0; j < 8; j++) {
                    uint32_t bhf[2];
                    uint32_t baddr = bt + ((lane & 15) * 136 + wn * 64 + j * 8) * 2;
                    ldsm2t(bhf, baddr);
#pragma unroll
                    for (int mi = 0; mi < 2; mi++) {
                        mma16816(accr[mi][j], af[mi], bhf);
                    }
                }
            }
            // ---- register epilogue: bias + per-warp online softmax partials ----
            int cb = half * 128 + wn * 64 + 2 * (lane & 3);
            float mx[4] = {-3e38f, -3e38f, -3e38f, -3e38f};
#pragma unroll
            for (int mi = 0; mi < 2; mi++)
#pragma unroll
                for (int j = 0; j < 8; j++) {
                    float2 bb = *(const float2*)((const float*)(sm + AB2) + cb + j * 8);
                    accr[mi][j][0] += bb.x; accr[mi][j][1] += bb.y;
                    accr[mi][j][2] += bb.x; accr[mi][j][3] += bb.y;
                    mx[mi * 2] = fmaxf(mx[mi * 2], fmaxf(accr[mi][j][0], accr[mi][j][1]));
                    mx[mi * 2 + 1] = fmaxf(mx[mi * 2 + 1], fmaxf(accr[mi][j][2], accr[mi][j][3]));
                }
#pragma unroll
            for (int s = 0; s < 4; s++) {
                mx[s] = fmaxf(mx[s], __shfl_xor_sync(0xffffffffu, mx[s], 1));
                mx[s] = fmaxf(mx[s], __shfl_xor_sync(0xffffffffu, mx[s], 2));
            }
            float zz[4] = {0.f, 0.f, 0.f, 0.f}, ss[4] = {0.f, 0.f, 0.f, 0.f};
            float sc[4] = {-3e38f, -3e38f, -3e38f, -3e38f};
#pragma unroll
            for (int mi = 0; mi < 2; mi++)
#pragma unroll
                for (int j = 0; j < 8; j++) {
                    int c0 = cb + j * 8;
                    int s0 = mi * 2, s1i = mi * 2 + 1;
                    float v0 = accr[mi][j][0], v1 = accr[mi][j][1];
                    float v2 = accr[mi][j][2], v3 = accr[mi][j][3];
                    float p0 = __expf(v0 - mx[s0]), p1 = __expf(v1 - mx[s0]);
                    float p2 = __expf(v2 - mx[s1i]), p3 = __expf(v3 - mx[s1i]);
                    zz[s0] += p0 + p1;  ss[s0] += v0 * p0 + v1 * p1;
                    zz[s1i] += p2 + p3; ss[s1i] += v2 * p2 + v3 * p3;
                    if (c0 == mact[s0]) sc[s0] = v0;
                    if (c0 + 1 == mact[s0]) sc[s0] = v1;
                    if (c0 == mact[s1i]) sc[s1i] = v2;
                    if (c0 + 1 == mact[s1i]) sc[s1i] = v3;
                }
#pragma unroll
            for (int s = 0; s < 4; s++) {
                zz[s] += __shfl_xor_sync(0xffffffffu, zz[s], 1);
                zz[s] += __shfl_xor_sync(0xffffffffu, zz[s], 2);
                ss[s] += __shfl_xor_sync(0xffffffffu, ss[s], 1);
                ss[s] += __shfl_xor_sync(0xffffffffu, ss[s], 2);
                sc[s] = fmaxf(sc[s], __shfl_xor_sync(0xffffffffu, sc[s], 1));
                sc[s] = fmaxf(sc[s], __shfl_xor_sync(0xffffffffu, sc[s], 2));
                float M = fmaxf(mrun[s], mx[s]);
                float e1 = __expf(mrun[s] - M), e2 = __expf(mx[s] - M);
                zrun[s] = zrun[s] * e1 + zz[s] * e2;
                s1run[s] = s1run[s] * e1 + ss[s] * e2;
                mrun[s] = M;
                schrun[s] = fmaxf(schrun[s], sc[s]);
            }
        }
        // ---- cross-warp (wn) merge via stg; wn==0 writes output ----
        __syncthreads();
        if (wn == 1 && (lane & 3) == 0) {
#pragma unroll
            for (int s = 0; s < 4; s++)
                *(float4*)(stg + rws[s] * 4) =
                    make_float4(mrun[s], zrun[s], s1run[s], schrun[s]);
        }
        __syncthreads();
        if (wn == 0 && (lane & 3) == 0) {
#pragma unroll
            for (int s = 0; s < 4; s++) {
                float4 o = *(const float4*)(stg + rws[s] * 4);
                float M = fmaxf(mrun[s], o.x);
                float e1 = __expf(mrun[s] - M), e2 = __expf(o.x - M);
                float z = zrun[s] * e1 + o.y * e2;
                float s1 = s1run[s] * e1 + o.z * e2;
                float sch = fmaxf(schrun[s], o.w);
                int rt = rws[s];
                if (r0 + rt < cnt) {
                    int b = ridx[rt];
                    float lz = M + __logf(z);
                    out[(size_t)b * 3 + 0] = sch - lz;
                    out[(size_t)b * 3 + 2] = s1 / z - lz;
                }
            }
        }
    } else {
        // ======== Critic [64 x 512 x 32], K-slice 16, 3-term, pipelined ========
        FragC acc[2];
        wmma::fill_fragment(acc[0], 0.f);
        wmma::fill_fragment(acc[1], 0.f);

        ldx8(xr, x, grow, 0, tid);
        stx8(sm, 0, xr, tid);
        ldx8(xr, x, grow, 1, tid);
        issue_cw(sm, 0, grp, 0, tid);
        CPC();

        for (int kc = 0; kc < 32; kc++) {
            int b = kc & 1;
            __syncthreads();  // (A)
            if (kc < 31) {
                issue_cw(sm, b ^ 1, grp, kc + 1, tid);
                CPC();
                CPW1();
            } else {
                CPW0();
            }
            __syncthreads();  // (B)
            const __nv_bfloat16* xh = (const __nv_bfloat16*)(sm + XS0 + b * 6144);
            const __nv_bfloat16* bh = (const __nv_bfloat16*)(sm + BT0 + b * 2560);
            FragA ah[2], al[2];
#pragma unroll
            for (int mi = 0; mi < 2; mi++) {
                wmma::load_matrix_sync(ah[mi], xh + (wm * 32 + mi * 16) * 24, 24);
                wmma::load_matrix_sync(al[mi], xh + 1536 + (wm * 32 + mi * 16) * 24, 24);
            }
            FragB fbh, fbl;
            wmma::load_matrix_sync(fbh, bh + wn * 16, 40);
            wmma::load_matrix_sync(fbl, bh + 640 + wn * 16, 40);
#pragma unroll
            for (int mi = 0; mi < 2; mi++) {
                wmma::mma_sync(acc[mi], ah[mi], fbh, acc[mi]);
                wmma::mma_sync(acc[mi], ah[mi], fbl, acc[mi]);
                wmma::mma_sync(acc[mi], al[mi], fbh, acc[mi]);
            }
            if (kc < 31) {
                stx8(sm, b ^ 1, xr, tid);
                if (kc < 30) ldx8(xr, x, grow, kc + 2, tid);
            }
        }
        __syncthreads();
#pragma unroll
        for (int mi = 0; mi < 2; mi++)
            wmma::store_matrix_sync(stg + (wm * 32 + mi * 16) * 36 + wn * 16, acc[mi], 36,
                                    wmma::mem_row_major);
        __syncthreads();
        {
            int row = tid >> 1, c0 = (tid & 1) * 16;
            const float4* hp = (const float4*)(stg + row * 36 + c0);
            const float4* b1p = (const float4*)((float*)(sm + CB1) + c0);
            const float4* w2p = (const float4*)((float*)(sm + CW2S) + c0);
            float sum = 0.f;
#pragma unroll
            for (int g = 0; g < 4; g++) {
                float4 h4 = hp[g], b4 = b1p[g], w4 = w2p[g];
                float h;
                h = h4.x + b4.x; sum += (h > 0.f ? h : 0.f) * w4.x;
                h = h4.y + b4.y; sum += (h > 0.f ? h : 0.f) * w4.y;
                h = h4.z + b4.z; sum += (h > 0.f ? h : 0.f) * w4.z;
                h = h4.w + b4.w; sum += (h > 0.f ? h : 0.f) * w4.w;
            }
            sum += __shfl_xor_sync(0xffffffffu, sum, 1);
            if ((tid & 1) == 0 && r0 + row < cnt)
                out[(size_t)ridx[row] * 3 + 1] = sum + Cb2[grp];
        }
    }
}

extern "C" void kernel_launch(void* const* d_in, const int* in_sizes, int n_in,
                              void* d_out, int out_size) {
    const float* x = (const float*)d_in[0];
    const int* commands = (const int*)d_in[1];
    const int* tasks = (const int*)d_in[2];
    const int* actions = (const int*)d_in[3];
    const float* A_W1 = (const float*)d_in[4];
    const float* A_b1 = (const float*)d_in[5];
    const float* A_W2 = (const float*)d_in[6];
    const float* A_b2 = (const float*)d_in[7];
    const float* C_W1 = (const float*)d_in[8];
    const float* C_b1 = (const float*)d_in[9];
    const float* C_W2 = (const float*)d_in[10];
    const float* C_b2 = (const float*)d_in[11];
    float* out = (float*)d_out;

    cudaFuncSetAttribute(fused_kernel, cudaFuncAttributeMaxDynamicSharedMemorySize,
                         SMEM_TOTAL);

    zero_kernel<<<1, 32>>>();
    route_kernel<<<Bn / 256, 256>>>(commands, tasks);
    int prep_elems = En * Fn * Hn + En * Hn * An + Tn * Fn * HCn;
    prep_kernel<<<(prep_elems + 255) / 256, 256>>>(A_W1, A_W2, C_W1);
    fused_kernel<<<dim3(NTILES_MAX, 1, 2), 128, SMEM_TOTAL>>>(
        x, actions, A_b1, A_b2, C_b1, C_W2, C_b2, out);
}